// round 1
// baseline (speedup 1.0000x reference)
#include <cuda_runtime.h>
#include <math.h>

#define L_   4
#define H_   4
#define B_   2
#define T_   1024
#define D_   1024
#define DFF_ 4096
#define V_   32000
#define M_   (B_*T_)   // 2048 tokens

// ---------------- scratch (static device globals; no allocs allowed) ----------
__device__ float g_h [M_*D_];         // residual stream
__device__ float g_xn[M_*D_];         // layernorm output
__device__ float g_q [H_*M_*D_];      // Q[h][m][e]
__device__ float g_k [H_*M_*D_];      // K[h][m][e]
__device__ float g_v [H_*M_*D_];      // V[h][m][e]
__device__ float g_s [B_*H_*T_*T_];   // S/A [b][h][t][s]
__device__ float g_y [M_*H_*D_];      // attention output, [m][h*D+e]
__device__ float g_ff[M_*DFF_];       // MLP hidden

// ---------------- block reductions --------------------------------------------
__device__ __forceinline__ float blockReduceSum(float v) {
    __shared__ float sh[9];
    int lane = threadIdx.x & 31, w = threadIdx.x >> 5;
    #pragma unroll
    for (int o = 16; o; o >>= 1) v += __shfl_xor_sync(0xffffffffu, v, o);
    if (lane == 0) sh[w] = v;
    __syncthreads();
    if (threadIdx.x == 0) {
        float s = 0.f;
        #pragma unroll
        for (int i = 0; i < 8; i++) s += sh[i];
        sh[8] = s;
    }
    __syncthreads();
    float r = sh[8];
    __syncthreads();
    return r;
}

__device__ __forceinline__ float blockReduceMax(float v) {
    __shared__ float sh[9];
    int lane = threadIdx.x & 31, w = threadIdx.x >> 5;
    #pragma unroll
    for (int o = 16; o; o >>= 1) v = fmaxf(v, __shfl_xor_sync(0xffffffffu, v, o));
    if (lane == 0) sh[w] = v;
    __syncthreads();
    if (threadIdx.x == 0) {
        float s = sh[0];
        #pragma unroll
        for (int i = 1; i < 8; i++) s = fmaxf(s, sh[i]);
        sh[8] = s;
    }
    __syncthreads();
    float r = sh[8];
    __syncthreads();
    return r;
}

// ---------------- embedding: token + sinusoidal positional --------------------
__global__ void embed_kernel(const int* __restrict__ x,
                             const float* __restrict__ emb,
                             float* __restrict__ h) {
    int m = blockIdx.x;            // 0..M_-1
    int t = m % T_;
    int tok = x[m];
    const float* erow = emb + (size_t)tok * D_;
    float* hrow = h + (size_t)m * D_;
    for (int d = threadIdx.x; d < D_; d += blockDim.x) {
        int i = d >> 1;
        float denom = powf(10000.f, (2.f * (float)i) / (float)D_);
        float ang = (float)t / denom;
        float pe = (d & 1) ? cosf(ang) : sinf(ang);
        hrow[d] = erow[d] + pe;
    }
}

// ---------------- layernorm (one block per row, D=1024, 256 thr x float4) -----
__global__ void layernorm_kernel(const float* __restrict__ in,
                                 float* __restrict__ out,
                                 const float* __restrict__ g,
                                 const float* __restrict__ b) {
    int m = blockIdx.x;
    int tid = threadIdx.x; // 256 threads, Dc/4 = 256 float4 per row
    const float4* x4 = (const float4*)(in + (size_t)m * D_);
    float4 v = x4[tid];
    float s = v.x + v.y + v.z + v.w;
    s = blockReduceSum(s);
    float mean = s * (1.0f / D_);
    float dx = v.x - mean, dy = v.y - mean, dz = v.z - mean, dw = v.w - mean;
    float q = dx*dx + dy*dy + dz*dz + dw*dw;
    q = blockReduceSum(q);
    float inv = rsqrtf(q * (1.0f / D_) + 1e-5f);
    float4 gg = ((const float4*)g)[tid];
    float4 bb = ((const float4*)b)[tid];
    float4 o;
    o.x = dx * inv * gg.x + bb.x;
    o.y = dy * inv * gg.y + bb.y;
    o.z = dz * inv * gg.z + bb.z;
    o.w = dw * inv * gg.w + bb.w;
    ((float4*)(out + (size_t)m * D_))[tid] = o;
}

// ---------------- causal masked softmax over S rows ---------------------------
// S = where(s<=t, S, -inf) * scale; softmax over s. Writes probabilities (0 for s>t).
__global__ void attn_softmax_kernel(float* __restrict__ S) {
    int r = blockIdx.x;            // 0 .. B*H*T-1
    int t = r % T_;
    int z = r / T_;
    float* row = S + (size_t)z * T_ * T_ + (size_t)t * T_;
    const float scale = 0.03125f;  // 1/sqrt(1024)
    int tid = threadIdx.x;
    float lmax = -INFINITY;
    for (int s = tid; s <= t; s += 256) lmax = fmaxf(lmax, row[s] * scale);
    float mx = blockReduceMax(lmax);
    float lsum = 0.f;
    for (int s = tid; s <= t; s += 256) lsum += expf(row[s] * scale - mx);
    float sum = blockReduceSum(lsum);
    float invs = 1.0f / sum;
    for (int s = tid; s < T_; s += 256)
        row[s] = (s <= t) ? expf(row[s] * scale - mx) * invs : 0.f;
}

// ---------------- final log-softmax over V=32000 -------------------------------
__global__ void logsoftmax_kernel(float* __restrict__ out) {
    float* row = out + (size_t)blockIdx.x * V_;
    int tid = threadIdx.x;
    float lmax = -INFINITY;
    for (int i = tid; i < V_; i += 256) lmax = fmaxf(lmax, row[i]);
    float mx = blockReduceMax(lmax);
    float lsum = 0.f;
    for (int i = tid; i < V_; i += 256) lsum += expf(row[i] - mx);
    float sum = blockReduceSum(lsum);
    float lse = logf(sum) + mx;
    for (int i = tid; i < V_; i += 256) row[i] -= lse;
}

// ---------------- generic batched GEMM (fp32 SIMT, 128x128x8, 8x8 microtile) --
// C = [residual +] act( A @ B(^T) + bias )
// Batch index z = zb*nH + zh; per-dim strides for A/B/C, bias strides over zh.
#define GF_ADDC 1
#define GF_GELU 2

template<bool TRANSB>
__global__ void __launch_bounds__(256, 2)
gemm_kernel(const float* __restrict__ A, const float* __restrict__ B,
            float* __restrict__ C, const float* __restrict__ bias,
            int M, int N, int K, int lda, int ldb, int ldc,
            long sAb, long sAh, long sBb, long sBh, long sCb, long sCh,
            long sBiash, int nH, int flags) {
    __shared__ float As[8][128];
    __shared__ float Bs[8][128];

    int z  = blockIdx.z;
    int zb = z / nH, zh = z % nH;
    A += (size_t)zb * sAb + (size_t)zh * sAh;
    B += (size_t)zb * sBb + (size_t)zh * sBh;
    C += (size_t)zb * sCb + (size_t)zh * sCh;
    if (bias) bias += (size_t)zh * sBiash;

    int tid = threadIdx.x;
    int bx = blockIdx.x, by = blockIdx.y;

    // A tile: 128 rows x 8 k; thread loads one float4
    int aRow = tid >> 1;
    int aCol = (tid & 1) << 2;
    const float* Ag = A + (size_t)(by * 128 + aRow) * lda + aCol;

    const float* Bg;
    int bRow, bCol;
    if (TRANSB) {               // B stored [N, K]
        bRow = tid >> 1;        // n in tile
        bCol = (tid & 1) << 2;  // k
        Bg = B + (size_t)(bx * 128 + bRow) * ldb + bCol;
    } else {                    // B stored [K, N]
        bRow = tid >> 5;        // k (0..7)
        bCol = (tid & 31) << 2; // n
        Bg = B + (size_t)bRow * ldb + bx * 128 + bCol;
    }

    float acc[8][8];
    #pragma unroll
    for (int i = 0; i < 8; i++)
        #pragma unroll
        for (int j = 0; j < 8; j++) acc[i][j] = 0.f;

    int tx = tid & 15, ty = tid >> 4;

    for (int k0 = 0; k0 < K; k0 += 8) {
        float4 av = *(const float4*)Ag; Ag += 8;
        As[aCol + 0][aRow] = av.x;
        As[aCol + 1][aRow] = av.y;
        As[aCol + 2][aRow] = av.z;
        As[aCol + 3][aRow] = av.w;
        if (TRANSB) {
            float4 bv = *(const float4*)Bg; Bg += 8;
            Bs[bCol + 0][bRow] = bv.x;
            Bs[bCol + 1][bRow] = bv.y;
            Bs[bCol + 2][bRow] = bv.z;
            Bs[bCol + 3][bRow] = bv.w;
        } else {
            float4 bv = *(const float4*)Bg; Bg += (size_t)8 * ldb;
            *(float4*)&Bs[bRow][bCol] = bv;
        }
        __syncthreads();
        #pragma unroll
        for (int kk = 0; kk < 8; kk++) {
            float ar[8], br[8];
            float4 a0 = *(const float4*)&As[kk][ty * 4];
            float4 a1 = *(const float4*)&As[kk][64 + ty * 4];
            float4 b0 = *(const float4*)&Bs[kk][tx * 4];
            float4 b1 = *(const float4*)&Bs[kk][64 + tx * 4];
            ar[0]=a0.x; ar[1]=a0.y; ar[2]=a0.z; ar[3]=a0.w;
            ar[4]=a1.x; ar[5]=a1.y; ar[6]=a1.z; ar[7]=a1.w;
            br[0]=b0.x; br[1]=b0.y; br[2]=b0.z; br[3]=b0.w;
            br[4]=b1.x; br[5]=b1.y; br[6]=b1.z; br[7]=b1.w;
            #pragma unroll
            for (int i = 0; i < 8; i++)
                #pragma unroll
                for (int j = 0; j < 8; j++)
                    acc[i][j] = fmaf(ar[i], br[j], acc[i][j]);
        }
        __syncthreads();
    }

    // epilogue: rows/cols split into two quadrants of 4
    #pragma unroll
    for (int i = 0; i < 8; i++) {
        int r = by * 128 + ((i < 4) ? (ty * 4 + i) : (64 + ty * 4 + i - 4));
        float* crow = C + (size_t)r * ldc;
        #pragma unroll
        for (int jq = 0; jq < 2; jq++) {
            int c = bx * 128 + jq * 64 + tx * 4;
            float vv[4];
            #pragma unroll
            for (int j = 0; j < 4; j++) vv[j] = acc[i][jq * 4 + j];
            if (bias) {
                float4 bb = *(const float4*)&bias[c];
                vv[0] += bb.x; vv[1] += bb.y; vv[2] += bb.z; vv[3] += bb.w;
            }
            if (flags & GF_GELU) {
                #pragma unroll
                for (int j = 0; j < 4; j++)
                    vv[j] = 0.5f * vv[j] * (1.0f + erff(vv[j] * 0.70710678118654752f));
            }
            if (flags & GF_ADDC) {
                float4 old = *(const float4*)&crow[c];
                vv[0] += old.x; vv[1] += old.y; vv[2] += old.z; vv[3] += old.w;
            }
            float4 o; o.x = vv[0]; o.y = vv[1]; o.z = vv[2]; o.w = vv[3];
            *(float4*)&crow[c] = o;
        }
    }
}

// ---------------- host-side launcher -------------------------------------------
static void launch_gemm(bool transB, const float* A, const float* B, float* C,
                        const float* bias, int M, int N, int K,
                        int lda, int ldb, int ldc,
                        long sAb, long sAh, long sBb, long sBh,
                        long sCb, long sCh, long sBiash,
                        int nB, int nH, int flags) {
    dim3 grid(N / 128, M / 128, nB * nH);
    if (transB)
        gemm_kernel<true><<<grid, 256>>>(A, B, C, bias, M, N, K, lda, ldb, ldc,
                                         sAb, sAh, sBb, sBh, sCb, sCh, sBiash, nH, flags);
    else
        gemm_kernel<false><<<grid, 256>>>(A, B, C, bias, M, N, K, lda, ldb, ldc,
                                          sAb, sAh, sBb, sBh, sCb, sCh, sBiash, nH, flags);
}

extern "C" void kernel_launch(void* const* d_in, const int* in_sizes, int n_in,
                              void* d_out, int out_size) {
    const int*   x         = (const int*)  d_in[0];
    const float* token_emb = (const float*)d_in[1];
    const float* Wq   = (const float*)d_in[2];
    const float* bq   = (const float*)d_in[3];
    const float* Wk   = (const float*)d_in[4];
    const float* bk   = (const float*)d_in[5];
    const float* Wv   = (const float*)d_in[6];
    const float* bv   = (const float*)d_in[7];
    const float* Wo   = (const float*)d_in[8];
    const float* bo   = (const float*)d_in[9];
    const float* ln1g = (const float*)d_in[10];
    const float* ln1b = (const float*)d_in[11];
    const float* ln2g = (const float*)d_in[12];
    const float* ln2b = (const float*)d_in[13];
    const float* W1   = (const float*)d_in[14];
    const float* b1   = (const float*)d_in[15];
    const float* W2   = (const float*)d_in[16];
    const float* b2   = (const float*)d_in[17];
    const float* flng = (const float*)d_in[18];
    const float* flnb = (const float*)d_in[19];
    const float* Wout = (const float*)d_in[20];
    float* out = (float*)d_out;

    float *ph, *pxn, *pq, *pk, *pv, *ps, *py, *pff;
    cudaGetSymbolAddress((void**)&ph,  g_h);
    cudaGetSymbolAddress((void**)&pxn, g_xn);
    cudaGetSymbolAddress((void**)&pq,  g_q);
    cudaGetSymbolAddress((void**)&pk,  g_k);
    cudaGetSymbolAddress((void**)&pv,  g_v);
    cudaGetSymbolAddress((void**)&ps,  g_s);
    cudaGetSymbolAddress((void**)&py,  g_y);
    cudaGetSymbolAddress((void**)&pff, g_ff);

    // 1) embedding
    embed_kernel<<<M_, 256>>>(x, token_emb, ph);

    for (int l = 0; l < L_; l++) {
        // 2) LN1
        layernorm_kernel<<<M_, 256>>>(ph, pxn, ln1g + (size_t)l * D_, ln1b + (size_t)l * D_);

        // 3) Q/K/V projections, batched over heads: Q[h] = xn @ Wq[l,h] + bq[l,h]
        const long wOff = (long)l * H_ * D_ * D_;
        const long bOff = (long)l * H_ * D_;
        launch_gemm(false, pxn, Wq + wOff, pq, bq + bOff,
                    M_, D_, D_, D_, D_, D_,
                    0, 0, 0, (long)D_ * D_, 0, (long)M_ * D_, D_, 1, H_, 0);
        launch_gemm(false, pxn, Wk + wOff, pk, bk + bOff,
                    M_, D_, D_, D_, D_, D_,
                    0, 0, 0, (long)D_ * D_, 0, (long)M_ * D_, D_, 1, H_, 0);
        launch_gemm(false, pxn, Wv + wOff, pv, bv + bOff,
                    M_, D_, D_, D_, D_, D_,
                    0, 0, 0, (long)D_ * D_, 0, (long)M_ * D_, D_, 1, H_, 0);

        // 4) S = Q @ K^T per (b,h)
        launch_gemm(true, pq, pk, ps, nullptr,
                    T_, T_, D_, D_, D_, T_,
                    (long)T_ * D_, (long)M_ * D_,        // A: Q
                    (long)T_ * D_, (long)M_ * D_,        // B: K (trans)
                    (long)H_ * T_ * T_, (long)T_ * T_,   // C: S[b][h]
                    0, B_, H_, 0);

        // 5) causal softmax (mask, scale 1/32)
        attn_softmax_kernel<<<B_ * H_ * T_, 256>>>(ps);

        // 6) y[m][h*D+e] = A @ V per (b,h)
        launch_gemm(false, ps, pv, py, nullptr,
                    T_, D_, T_, T_, D_, H_ * D_,
                    (long)H_ * T_ * T_, (long)T_ * T_,   // A: S
                    (long)T_ * D_, (long)M_ * D_,        // B: V
                    (long)T_ * H_ * D_, (long)D_,        // C: y
                    0, B_, H_, 0);

        // 7) h += y @ Wo[l] + bo[l]
        launch_gemm(false, py, Wo + (long)l * H_ * D_ * D_, ph, bo + (long)l * D_,
                    M_, D_, H_ * D_, H_ * D_, D_, D_,
                    0, 0, 0, 0, 0, 0, 0, 1, 1, GF_ADDC);

        // 8) LN2
        layernorm_kernel<<<M_, 256>>>(ph, pxn, ln2g + (size_t)l * D_, ln2b + (size_t)l * D_);

        // 9) ff = gelu(xn @ W1[l] + b1[l])
        launch_gemm(false, pxn, W1 + (long)l * D_ * DFF_, pff, b1 + (long)l * DFF_,
                    M_, DFF_, D_, D_, DFF_, DFF_,
                    0, 0, 0, 0, 0, 0, 0, 1, 1, GF_GELU);

        // 10) h += ff @ W2[l] + b2[l]
        launch_gemm(false, pff, W2 + (long)l * DFF_ * D_, ph, b2 + (long)l * D_,
                    M_, D_, DFF_, DFF_, D_, D_,
                    0, 0, 0, 0, 0, 0, 0, 1, 1, GF_ADDC);
    }

    // 11) final LN
    layernorm_kernel<<<M_, 256>>>(ph, pxn, flng, flnb);

    // 12) logits = xn @ Wout  (straight into d_out)
    launch_gemm(false, pxn, Wout, out, nullptr,
                M_, V_, D_, D_, V_, V_,
                0, 0, 0, 0, 0, 0, 0, 1, 1, 0);

    // 13) in-place log_softmax over V
    logsoftmax_kernel<<<M_, 256>>>(out);
}

// round 2
// speedup vs baseline: 1.1189x; 1.1189x over previous
#include <cuda_runtime.h>
#include <math.h>

#define L_   4
#define H_   4
#define B_   2
#define T_   1024
#define D_   1024
#define DFF_ 4096
#define V_   32000
#define M_   (B_*T_)   // 2048 tokens

// ---------------- scratch (static device globals; no allocs allowed) ----------
__device__ float g_h [M_*D_];         // residual stream
__device__ float g_xn[M_*D_];         // layernorm output
__device__ float g_q [H_*M_*D_];      // Q[h][m][e]
__device__ float g_k [H_*M_*D_];      // K[h][m][e]
__device__ float g_v [H_*M_*D_];      // V[h][m][e]
__device__ float g_s [B_*H_*T_*T_];   // S/A [b][h][t][s]
__device__ float g_y [M_*H_*D_];      // attention output, [m][h*D+e]
__device__ float g_ff[M_*DFF_];       // MLP hidden

// ---------------- packed f32x2 FMA (SASS FFMA2; ptxas never emits from C++) ---
__device__ __forceinline__ void ffma2(float2& c, const float2 a, const float2 b) {
    asm("fma.rn.f32x2 %0, %1, %2, %0;"
        : "+l"(reinterpret_cast<unsigned long long&>(c))
        : "l"(reinterpret_cast<const unsigned long long&>(a)),
          "l"(reinterpret_cast<const unsigned long long&>(b)));
}

// ---------------- block reductions --------------------------------------------
__device__ __forceinline__ float blockReduceSum(float v) {
    __shared__ float sh[9];
    int lane = threadIdx.x & 31, w = threadIdx.x >> 5;
    #pragma unroll
    for (int o = 16; o; o >>= 1) v += __shfl_xor_sync(0xffffffffu, v, o);
    if (lane == 0) sh[w] = v;
    __syncthreads();
    if (threadIdx.x == 0) {
        float s = 0.f;
        #pragma unroll
        for (int i = 0; i < 8; i++) s += sh[i];
        sh[8] = s;
    }
    __syncthreads();
    float r = sh[8];
    __syncthreads();
    return r;
}

__device__ __forceinline__ float blockReduceMax(float v) {
    __shared__ float sh[9];
    int lane = threadIdx.x & 31, w = threadIdx.x >> 5;
    #pragma unroll
    for (int o = 16; o; o >>= 1) v = fmaxf(v, __shfl_xor_sync(0xffffffffu, v, o));
    if (lane == 0) sh[w] = v;
    __syncthreads();
    if (threadIdx.x == 0) {
        float s = sh[0];
        #pragma unroll
        for (int i = 1; i < 8; i++) s = fmaxf(s, sh[i]);
        sh[8] = s;
    }
    __syncthreads();
    float r = sh[8];
    __syncthreads();
    return r;
}

// ---------------- embedding: token + sinusoidal positional --------------------
__global__ void embed_kernel(const int* __restrict__ x,
                             const float* __restrict__ emb,
                             float* __restrict__ h) {
    int m = blockIdx.x;            // 0..M_-1
    int t = m % T_;
    int tok = x[m];
    const float* erow = emb + (size_t)tok * D_;
    float* hrow = h + (size_t)m * D_;
    for (int d = threadIdx.x; d < D_; d += blockDim.x) {
        int i = d >> 1;
        float denom = powf(10000.f, (2.f * (float)i) / (float)D_);
        float ang = (float)t / denom;
        float pe = (d & 1) ? cosf(ang) : sinf(ang);
        hrow[d] = erow[d] + pe;
    }
}

// ---------------- layernorm (one block per row, D=1024, 256 thr x float4) -----
__global__ void layernorm_kernel(const float* __restrict__ in,
                                 float* __restrict__ out,
                                 const float* __restrict__ g,
                                 const float* __restrict__ b) {
    int m = blockIdx.x;
    int tid = threadIdx.x;
    const float4* x4 = (const float4*)(in + (size_t)m * D_);
    float4 v = x4[tid];
    float s = v.x + v.y + v.z + v.w;
    s = blockReduceSum(s);
    float mean = s * (1.0f / D_);
    float dx = v.x - mean, dy = v.y - mean, dz = v.z - mean, dw = v.w - mean;
    float q = dx*dx + dy*dy + dz*dz + dw*dw;
    q = blockReduceSum(q);
    float inv = rsqrtf(q * (1.0f / D_) + 1e-5f);
    float4 gg = ((const float4*)g)[tid];
    float4 bb = ((const float4*)b)[tid];
    float4 o;
    o.x = dx * inv * gg.x + bb.x;
    o.y = dy * inv * gg.y + bb.y;
    o.z = dz * inv * gg.z + bb.z;
    o.w = dw * inv * gg.w + bb.w;
    ((float4*)(out + (size_t)m * D_))[tid] = o;
}

// ---------------- causal masked softmax over S rows ---------------------------
__global__ void attn_softmax_kernel(float* __restrict__ S) {
    int r = blockIdx.x;            // 0 .. B*H*T-1
    int t = r % T_;
    int z = r / T_;
    float* row = S + (size_t)z * T_ * T_ + (size_t)t * T_;
    const float scale = 0.03125f;  // 1/sqrt(1024)
    int tid = threadIdx.x;
    float lmax = -INFINITY;
    for (int s = tid; s <= t; s += 256) lmax = fmaxf(lmax, row[s] * scale);
    float mx = blockReduceMax(lmax);
    float lsum = 0.f;
    for (int s = tid; s <= t; s += 256) lsum += expf(row[s] * scale - mx);
    float sum = blockReduceSum(lsum);
    float invs = 1.0f / sum;
    for (int s = tid; s < T_; s += 256)
        row[s] = (s <= t) ? expf(row[s] * scale - mx) * invs : 0.f;
}

// ---------------- final log-softmax over V=32000 -------------------------------
__global__ void logsoftmax_kernel(float* __restrict__ out) {
    float* row = out + (size_t)blockIdx.x * V_;
    int tid = threadIdx.x;
    float lmax = -INFINITY;
    for (int i = tid; i < V_; i += 256) lmax = fmaxf(lmax, row[i]);
    float mx = blockReduceMax(lmax);
    float lsum = 0.f;
    for (int i = tid; i < V_; i += 256) lsum += expf(row[i] - mx);
    float sum = blockReduceSum(lsum);
    float lse = logf(sum) + mx;
    for (int i = tid; i < V_; i += 256) row[i] -= lse;
}

// ---------------- batched GEMM: fp32, FFMA2, double-buffered, 128x128x8 -------
// C = [residual +] act( A @ B(^T) + bias ), batch z = zb*nH+zh
#define GF_ADDC   1
#define GF_GELU   2
#define GF_CAUSAL 4   // skip blocks entirely above the causal diagonal (S=QK^T)
#define GF_KLIM   8   // limit K to (by+1)*128 (A@V with causal-zero A)

template<bool TRANSB>
__global__ void __launch_bounds__(256, 2)
gemm_kernel(const float* __restrict__ A, const float* __restrict__ B,
            float* __restrict__ C, const float* __restrict__ bias,
            int M, int N, int K, int lda, int ldb, int ldc,
            long sAb, long sAh, long sBb, long sBh, long sCb, long sCh,
            long sBiash, int nH, int flags) {
    int bx = blockIdx.x, by = blockIdx.y;
    if ((flags & GF_CAUSAL) && bx > by) return;
    if (flags & GF_KLIM) K = min(K, (by + 1) * 128);

    // As duplicated along rows: As[buf][k][2r+{0,1}] = A[r][k]  -> packed (a,a)
    __shared__ float As[2][8][256];
    __shared__ float Bs[2][8][128];

    int z  = blockIdx.z;
    int zb = z / nH, zh = z % nH;
    A += (size_t)zb * sAb + (size_t)zh * sAh;
    B += (size_t)zb * sBb + (size_t)zh * sBh;
    C += (size_t)zb * sCb + (size_t)zh * sCh;
    if (bias) bias += (size_t)zh * sBiash;

    int tid = threadIdx.x;

    int aRow = tid >> 1;
    int aCol = (tid & 1) << 2;
    const float* Ag = A + (size_t)(by * 128 + aRow) * lda + aCol;

    const float* Bg;
    int bRow, bCol;
    if (TRANSB) {               // B stored [N, K]
        bRow = tid >> 1;
        bCol = (tid & 1) << 2;
        Bg = B + (size_t)(bx * 128 + bRow) * ldb + bCol;
    } else {                    // B stored [K, N]
        bRow = tid >> 5;
        bCol = (tid & 31) << 2;
        Bg = B + (size_t)bRow * ldb + bx * 128 + bCol;
    }

    float2 acc[8][4];
    #pragma unroll
    for (int i = 0; i < 8; i++)
        #pragma unroll
        for (int j = 0; j < 4; j++) acc[i][j] = make_float2(0.f, 0.f);

    const int tx = tid & 15, ty = tid >> 4;

    auto stage = [&](int buf, float4 av, float4 bv) {
        *(float2*)&As[buf][aCol + 0][2 * aRow] = make_float2(av.x, av.x);
        *(float2*)&As[buf][aCol + 1][2 * aRow] = make_float2(av.y, av.y);
        *(float2*)&As[buf][aCol + 2][2 * aRow] = make_float2(av.z, av.z);
        *(float2*)&As[buf][aCol + 3][2 * aRow] = make_float2(av.w, av.w);
        if (TRANSB) {
            Bs[buf][bCol + 0][bRow] = bv.x;
            Bs[buf][bCol + 1][bRow] = bv.y;
            Bs[buf][bCol + 2][bRow] = bv.z;
            Bs[buf][bCol + 3][bRow] = bv.w;
        } else {
            *(float4*)&Bs[buf][bRow][bCol] = bv;
        }
    };

    auto compute = [&](int buf) {
        #pragma unroll
        for (int kk = 0; kk < 8; kk++) {
            float4 a01 = *(const float4*)&As[buf][kk][8 * ty];
            float4 a23 = *(const float4*)&As[buf][kk][8 * ty + 4];
            float4 a45 = *(const float4*)&As[buf][kk][128 + 8 * ty];
            float4 a67 = *(const float4*)&As[buf][kk][128 + 8 * ty + 4];
            float4 b03 = *(const float4*)&Bs[buf][kk][4 * tx];
            float4 b47 = *(const float4*)&Bs[buf][kk][64 + 4 * tx];
            float2 aa[8], bb[4];
            aa[0] = make_float2(a01.x, a01.y); aa[1] = make_float2(a01.z, a01.w);
            aa[2] = make_float2(a23.x, a23.y); aa[3] = make_float2(a23.z, a23.w);
            aa[4] = make_float2(a45.x, a45.y); aa[5] = make_float2(a45.z, a45.w);
            aa[6] = make_float2(a67.x, a67.y); aa[7] = make_float2(a67.z, a67.w);
            bb[0] = make_float2(b03.x, b03.y); bb[1] = make_float2(b03.z, b03.w);
            bb[2] = make_float2(b47.x, b47.y); bb[3] = make_float2(b47.z, b47.w);
            #pragma unroll
            for (int i = 0; i < 8; i++)
                #pragma unroll
                for (int j = 0; j < 4; j++)
                    ffma2(acc[i][j], aa[i], bb[j]);
        }
    };

    // prologue: stage tile 0
    {
        float4 av = *(const float4*)Ag; Ag += 8;
        float4 bv = *(const float4*)Bg;
        if (TRANSB) Bg += 8; else Bg += (size_t)8 * ldb;
        stage(0, av, bv);
    }
    __syncthreads();

    int cur = 0;
    int ktiles = K >> 3;
    for (int kt = 1; kt < ktiles; kt++) {
        float4 av = *(const float4*)Ag; Ag += 8;
        float4 bv = *(const float4*)Bg;
        if (TRANSB) Bg += 8; else Bg += (size_t)8 * ldb;
        compute(cur);
        stage(cur ^ 1, av, bv);
        __syncthreads();
        cur ^= 1;
    }
    compute(cur);

    // epilogue
    #pragma unroll
    for (int i = 0; i < 8; i++) {
        int r = by * 128 + ((i < 4) ? (ty * 4 + i) : (64 + ty * 4 + i - 4));
        float* crow = C + (size_t)r * ldc;
        #pragma unroll
        for (int jq = 0; jq < 2; jq++) {
            int c = bx * 128 + jq * 64 + tx * 4;
            float vv[4];
            vv[0] = acc[i][jq * 2 + 0].x; vv[1] = acc[i][jq * 2 + 0].y;
            vv[2] = acc[i][jq * 2 + 1].x; vv[3] = acc[i][jq * 2 + 1].y;
            if (bias) {
                float4 bbv = *(const float4*)&bias[c];
                vv[0] += bbv.x; vv[1] += bbv.y; vv[2] += bbv.z; vv[3] += bbv.w;
            }
            if (flags & GF_GELU) {
                #pragma unroll
                for (int j = 0; j < 4; j++)
                    vv[j] = 0.5f * vv[j] * (1.0f + erff(vv[j] * 0.70710678118654752f));
            }
            if (flags & GF_ADDC) {
                float4 old = *(const float4*)&crow[c];
                vv[0] += old.x; vv[1] += old.y; vv[2] += old.z; vv[3] += old.w;
            }
            float4 o; o.x = vv[0]; o.y = vv[1]; o.z = vv[2]; o.w = vv[3];
            *(float4*)&crow[c] = o;
        }
    }
}

// ---------------- host-side launcher -------------------------------------------
static void launch_gemm(bool transB, const float* A, const float* B, float* C,
                        const float* bias, int M, int N, int K,
                        int lda, int ldb, int ldc,
                        long sAb, long sAh, long sBb, long sBh,
                        long sCb, long sCh, long sBiash,
                        int nB, int nH, int flags) {
    dim3 grid(N / 128, M / 128, nB * nH);
    if (transB)
        gemm_kernel<true><<<grid, 256>>>(A, B, C, bias, M, N, K, lda, ldb, ldc,
                                         sAb, sAh, sBb, sBh, sCb, sCh, sBiash, nH, flags);
    else
        gemm_kernel<false><<<grid, 256>>>(A, B, C, bias, M, N, K, lda, ldb, ldc,
                                          sAb, sAh, sBb, sBh, sCb, sCh, sBiash, nH, flags);
}

extern "C" void kernel_launch(void* const* d_in, const int* in_sizes, int n_in,
                              void* d_out, int out_size) {
    const int*   x         = (const int*)  d_in[0];
    const float* token_emb = (const float*)d_in[1];
    const float* Wq   = (const float*)d_in[2];
    const float* bq   = (const float*)d_in[3];
    const float* Wk   = (const float*)d_in[4];
    const float* bk   = (const float*)d_in[5];
    const float* Wv   = (const float*)d_in[6];
    const float* bv   = (const float*)d_in[7];
    const float* Wo   = (const float*)d_in[8];
    const float* bo   = (const float*)d_in[9];
    const float* ln1g = (const float*)d_in[10];
    const float* ln1b = (const float*)d_in[11];
    const float* ln2g = (const float*)d_in[12];
    const float* ln2b = (const float*)d_in[13];
    const float* W1   = (const float*)d_in[14];
    const float* b1   = (const float*)d_in[15];
    const float* W2   = (const float*)d_in[16];
    const float* b2   = (const float*)d_in[17];
    const float* flng = (const float*)d_in[18];
    const float* flnb = (const float*)d_in[19];
    const float* Wout = (const float*)d_in[20];
    float* out = (float*)d_out;

    float *ph, *pxn, *pq, *pk, *pv, *ps, *py, *pff;
    cudaGetSymbolAddress((void**)&ph,  g_h);
    cudaGetSymbolAddress((void**)&pxn, g_xn);
    cudaGetSymbolAddress((void**)&pq,  g_q);
    cudaGetSymbolAddress((void**)&pk,  g_k);
    cudaGetSymbolAddress((void**)&pv,  g_v);
    cudaGetSymbolAddress((void**)&ps,  g_s);
    cudaGetSymbolAddress((void**)&py,  g_y);
    cudaGetSymbolAddress((void**)&pff, g_ff);

    // 1) embedding
    embed_kernel<<<M_, 256>>>(x, token_emb, ph);

    for (int l = 0; l < L_; l++) {
        // 2) LN1
        layernorm_kernel<<<M_, 256>>>(ph, pxn, ln1g + (size_t)l * D_, ln1b + (size_t)l * D_);

        // 3) Q/K/V projections, batched over heads
        const long wOff = (long)l * H_ * D_ * D_;
        const long bOff = (long)l * H_ * D_;
        launch_gemm(false, pxn, Wq + wOff, pq, bq + bOff,
                    M_, D_, D_, D_, D_, D_,
                    0, 0, 0, (long)D_ * D_, 0, (long)M_ * D_, D_, 1, H_, 0);
        launch_gemm(false, pxn, Wk + wOff, pk, bk + bOff,
                    M_, D_, D_, D_, D_, D_,
                    0, 0, 0, (long)D_ * D_, 0, (long)M_ * D_, D_, 1, H_, 0);
        launch_gemm(false, pxn, Wv + wOff, pv, bv + bOff,
                    M_, D_, D_, D_, D_, D_,
                    0, 0, 0, (long)D_ * D_, 0, (long)M_ * D_, D_, 1, H_, 0);

        // 4) S = Q @ K^T per (b,h), skipping fully-masked blocks
        launch_gemm(true, pq, pk, ps, nullptr,
                    T_, T_, D_, D_, D_, T_,
                    (long)T_ * D_, (long)M_ * D_,
                    (long)T_ * D_, (long)M_ * D_,
                    (long)H_ * T_ * T_, (long)T_ * T_,
                    0, B_, H_, GF_CAUSAL);

        // 5) causal softmax
        attn_softmax_kernel<<<B_ * H_ * T_, 256>>>(ps);

        // 6) y = A @ V per (b,h), K clamped to causal extent
        launch_gemm(false, ps, pv, py, nullptr,
                    T_, D_, T_, T_, D_, H_ * D_,
                    (long)H_ * T_ * T_, (long)T_ * T_,
                    (long)T_ * D_, (long)M_ * D_,
                    (long)T_ * H_ * D_, (long)D_,
                    0, B_, H_, GF_KLIM);

        // 7) h += y @ Wo[l] + bo[l]
        launch_gemm(false, py, Wo + (long)l * H_ * D_ * D_, ph, bo + (long)l * D_,
                    M_, D_, H_ * D_, H_ * D_, D_, D_,
                    0, 0, 0, 0, 0, 0, 0, 1, 1, GF_ADDC);

        // 8) LN2
        layernorm_kernel<<<M_, 256>>>(ph, pxn, ln2g + (size_t)l * D_, ln2b + (size_t)l * D_);

        // 9) ff = gelu(xn @ W1[l] + b1[l])
        launch_gemm(false, pxn, W1 + (long)l * D_ * DFF_, pff, b1 + (long)l * DFF_,
                    M_, DFF_, D_, D_, DFF_, DFF_,
                    0, 0, 0, 0, 0, 0, 0, 1, 1, GF_GELU);

        // 10) h += ff @ W2[l] + b2[l]
        launch_gemm(false, pff, W2 + (long)l * DFF_ * D_, ph, b2 + (long)l * D_,
                    M_, D_, DFF_, DFF_, D_, D_,
                    0, 0, 0, 0, 0, 0, 0, 1, 1, GF_ADDC);
    }

    // 11) final LN
    layernorm_kernel<<<M_, 256>>>(ph, pxn, flng, flnb);

    // 12) logits = xn @ Wout  (straight into d_out)
    launch_gemm(false, pxn, Wout, out, nullptr,
                M_, V_, D_, D_, V_, V_,
                0, 0, 0, 0, 0, 0, 0, 1, 1, 0);

    // 13) in-place log_softmax over V
    logsoftmax_kernel<<<M_, 256>>>(out);
}

// round 4
// speedup vs baseline: 1.8434x; 1.6475x over previous
#include <cuda_runtime.h>
#include <cstdint>
#include <math.h>

#define L_   4
#define H_   4
#define B_   2
#define T_   1024
#define D_   1024
#define DFF_ 4096
#define V_   32000
#define M_   (B_*T_)   // 2048 tokens

// ---------------- scratch (static device globals; no allocs allowed) ----------
__device__ float g_h [M_*D_];
__device__ float g_xn[M_*D_];
__device__ float g_q [H_*M_*D_];
__device__ float g_k [H_*M_*D_];
__device__ float g_v [H_*M_*D_];
__device__ float g_s [B_*H_*T_*T_];
__device__ float g_y [M_*H_*D_];
__device__ float g_ff[M_*DFF_];

// ---------------- tf32 helpers --------------------------------------------------
__device__ __forceinline__ uint32_t to_tf32(float f) {
    uint32_t u;
    asm("cvt.rna.tf32.f32 %0, %1;" : "=r"(u) : "f"(f));
    return u;
}
__device__ __forceinline__ void mma_tf32(float* c, const uint32_t* a, const uint32_t* b) {
    asm volatile("mma.sync.aligned.m16n8k8.row.col.f32.tf32.tf32.f32 "
        "{%0,%1,%2,%3}, {%4,%5,%6,%7}, {%8,%9}, {%0,%1,%2,%3};"
        : "+f"(c[0]), "+f"(c[1]), "+f"(c[2]), "+f"(c[3])
        : "r"(a[0]), "r"(a[1]), "r"(a[2]), "r"(a[3]), "r"(b[0]), "r"(b[1]));
}

// ---------------- fast exp on the FMA pipe --------------------------------------
__device__ __forceinline__ float fexp(float x) {
    x = fmaxf(x, -80.f);
    float z = x * 1.4426950408889634f;
    float y = z + 12582912.0f;
    float n = y - 12582912.0f;
    float t = fmaf(n, -0.6931471805599453f, x);
    float p =             0.008333333f;
    p = fmaf(p, t, 0.041666668f);
    p = fmaf(p, t, 0.16666667f);
    p = fmaf(p, t, 0.5f);
    p = fmaf(p, t, 1.0f);
    p = fmaf(p, t, 1.0f);
    int e = __float_as_int(y) - 0x4B400000;
    return p * __int_as_float((127 + e) << 23);
}

// ---------------- block reductions ----------------------------------------------
__device__ __forceinline__ float blockReduceSum(float v) {
    __shared__ float sh[9];
    int lane = threadIdx.x & 31, w = threadIdx.x >> 5;
    #pragma unroll
    for (int o = 16; o; o >>= 1) v += __shfl_xor_sync(0xffffffffu, v, o);
    if (lane == 0) sh[w] = v;
    __syncthreads();
    if (threadIdx.x == 0) {
        float s = 0.f;
        #pragma unroll
        for (int i = 0; i < 8; i++) s += sh[i];
        sh[8] = s;
    }
    __syncthreads();
    float r = sh[8];
    __syncthreads();
    return r;
}
__device__ __forceinline__ float blockReduceMax(float v) {
    __shared__ float sh[9];
    int lane = threadIdx.x & 31, w = threadIdx.x >> 5;
    #pragma unroll
    for (int o = 16; o; o >>= 1) v = fmaxf(v, __shfl_xor_sync(0xffffffffu, v, o));
    if (lane == 0) sh[w] = v;
    __syncthreads();
    if (threadIdx.x == 0) {
        float s = sh[0];
        #pragma unroll
        for (int i = 1; i < 8; i++) s = fmaxf(s, sh[i]);
        sh[8] = s;
    }
    __syncthreads();
    float r = sh[8];
    __syncthreads();
    return r;
}

// ---------------- embedding ------------------------------------------------------
__global__ void embed_kernel(const int* __restrict__ x,
                             const float* __restrict__ emb,
                             float* __restrict__ h) {
    int m = blockIdx.x;
    int t = m % T_;
    int tok = x[m];
    const float* erow = emb + (size_t)tok * D_;
    float* hrow = h + (size_t)m * D_;
    for (int d = threadIdx.x; d < D_; d += blockDim.x) {
        int i = d >> 1;
        float denom = powf(10000.f, (2.f * (float)i) / (float)D_);
        float ang = (float)t / denom;
        float pe = (d & 1) ? cosf(ang) : sinf(ang);
        hrow[d] = erow[d] + pe;
    }
}

// ---------------- layernorm -------------------------------------------------------
__global__ void layernorm_kernel(const float* __restrict__ in,
                                 float* __restrict__ out,
                                 const float* __restrict__ g,
                                 const float* __restrict__ b) {
    int m = blockIdx.x;
    int tid = threadIdx.x;
    const float4* x4 = (const float4*)(in + (size_t)m * D_);
    float4 v = x4[tid];
    float s = v.x + v.y + v.z + v.w;
    s = blockReduceSum(s);
    float mean = s * (1.0f / D_);
    float dx = v.x - mean, dy = v.y - mean, dz = v.z - mean, dw = v.w - mean;
    float q = dx*dx + dy*dy + dz*dz + dw*dw;
    q = blockReduceSum(q);
    float inv = rsqrtf(q * (1.0f / D_) + 1e-5f);
    float4 gg = ((const float4*)g)[tid];
    float4 bb = ((const float4*)b)[tid];
    float4 o;
    o.x = dx * inv * gg.x + bb.x;
    o.y = dy * inv * gg.y + bb.y;
    o.z = dz * inv * gg.z + bb.z;
    o.w = dw * inv * gg.w + bb.w;
    ((float4*)(out + (size_t)m * D_))[tid] = o;
}

// ---------------- causal softmax ---------------------------------------------------
__global__ void attn_softmax_kernel(float* __restrict__ S) {
    int r = blockIdx.x;            // 0 .. B*H*T-1
    int t = r % T_;
    int z = r / T_;
    float* row = S + (size_t)z * T_ * T_ + (size_t)t * T_;
    const float scale = 0.03125f;  // 1/sqrt(1024)
    int tid = threadIdx.x;
    float v[4];
    #pragma unroll
    for (int i = 0; i < 4; i++) {
        int s = tid + 256 * i;
        v[i] = (s <= t) ? row[s] * scale : -INFINITY;
    }
    float lmax = fmaxf(fmaxf(v[0], v[1]), fmaxf(v[2], v[3]));
    float mx = blockReduceMax(lmax);
    float e[4]; float lsum = 0.f;
    #pragma unroll
    for (int i = 0; i < 4; i++) {
        int s = tid + 256 * i;
        e[i] = (s <= t) ? fexp(v[i] - mx) : 0.f;
        lsum += e[i];
    }
    float sum = blockReduceSum(lsum);
    float invs = 1.0f / sum;
    #pragma unroll
    for (int i = 0; i < 4; i++) {
        int s = tid + 256 * i;
        row[s] = e[i] * invs;
    }
}

// ---------------- final log-softmax -------------------------------------------------
__global__ void logsoftmax_kernel(float* __restrict__ out) {
    float* row = out + (size_t)blockIdx.x * V_;
    int tid = threadIdx.x;
    float lmax = -INFINITY;
    for (int i = tid; i < V_; i += 256) lmax = fmaxf(lmax, row[i]);
    float mx = blockReduceMax(lmax);
    float lsum = 0.f;
    for (int i = tid; i < V_; i += 256) lsum += fexp(row[i] - mx);
    float sum = blockReduceSum(lsum);
    float lse = logf(sum) + mx;
    for (int i = tid; i < V_; i += 256) row[i] -= lse;
}

// ---------------- HMMA tf32 batched GEMM --------------------------------------------
// C = [residual +] act( A @ B(^T) + bias ), batch z = zb*nH+zh
// CTA 128x128, K-tile 32, 8 warps (2m x 4n), warp 64x32 via m16n8k8 tf32 HMMA.
// SMEM tiles [row][32] uint32 (tf32), XOR swizzle c ^= (row&7)<<2, double-buffered.
#define GF_ADDC   1
#define GF_GELU   2
#define GF_CAUSAL 4
#define GF_KLIM   8

#define SMEM_REQ (4 * 4096 * 4)   // A0 A1 B0 B1, 4096 u32 each = 64KB

template<bool TRANSB>
__global__ void __launch_bounds__(256)
hmma_gemm(const float* __restrict__ A, const float* __restrict__ B,
          float* __restrict__ C, const float* __restrict__ bias,
          int M, int N, int K, int lda, int ldb, int ldc,
          long sAb, long sAh, long sBb, long sBh, long sCb, long sCh,
          long sBiash, int nH, int flags) {
    int bx = blockIdx.x, by = blockIdx.y;
    if ((flags & GF_CAUSAL) && bx > by) return;
    if (flags & GF_KLIM) K = min(K, (by + 1) * 128);

    extern __shared__ uint32_t sm[];
    uint32_t* As[2] = { sm,        sm + 4096 };
    uint32_t* Bs[2] = { sm + 8192, sm + 12288 };

    int z  = blockIdx.z;
    int zb = z / nH, zh = z % nH;
    A += (size_t)zb * sAb + (size_t)zh * sAh;
    B += (size_t)zb * sBb + (size_t)zh * sBh;
    C += (size_t)zb * sCb + (size_t)zh * sCh;
    if (bias) bias += (size_t)zh * sBiash;

    const int tid = threadIdx.x;
    const int wid = tid >> 5, lane = tid & 31;
    const int lr = lane >> 2, lc = lane & 3;
    const int wm = wid & 1, wn = wid >> 1;      // warp tile: rows wm*64, cols wn*32
    const int swz = lr << 2;

    // staging maps
    const int sr = tid >> 1;                    // row 0..127
    const int kh = (tid & 1) << 4;              // k-half 0/16
    const float* Aptr = A + (size_t)(by * 128 + sr) * lda + kh;
    const float* Bdir = TRANSB ? (B + (size_t)(bx * 128 + sr) * ldb + kh) : nullptr;

    float acc[4][4][4];
    #pragma unroll
    for (int i = 0; i < 4; i++)
        #pragma unroll
        for (int j = 0; j < 4; j++)
            #pragma unroll
            for (int q = 0; q < 4; q++) acc[i][j][q] = 0.f;

    auto loadA = [&](int kt, float4* av) {
        const float* s = Aptr + kt * 32;
        #pragma unroll
        for (int j = 0; j < 4; j++) av[j] = *(const float4*)(s + 4 * j);
    };
    auto loadB = [&](int kt, float4* bv) {
        if (TRANSB) {
            const float* s = Bdir + kt * 32;
            #pragma unroll
            for (int j = 0; j < 4; j++) bv[j] = *(const float4*)(s + 4 * j);
        } else {
            #pragma unroll
            for (int it = 0; it < 4; it++) {
                int task = wid + 8 * it;          // 0..31
                int nb = (task & 3) << 5;
                int kq = (task >> 2) << 2;
                int n  = nb + lane;
                const float* s = B + (size_t)(kt * 32 + kq) * ldb + (size_t)bx * 128 + n;
                bv[it] = make_float4(s[0], s[(size_t)ldb], s[2 * (size_t)ldb], s[3 * (size_t)ldb]);
            }
        }
    };
    auto stage = [&](int buf, const float4* av, const float4* bv) {
        uint32_t* Ad = As[buf];
        #pragma unroll
        for (int j = 0; j < 4; j++) {
            int c0 = (kh + 4 * j) ^ ((sr & 7) << 2);
            uint4 u = { to_tf32(av[j].x), to_tf32(av[j].y), to_tf32(av[j].z), to_tf32(av[j].w) };
            *(uint4*)&Ad[sr * 32 + c0] = u;
        }
        uint32_t* Bd = Bs[buf];
        if (TRANSB) {
            #pragma unroll
            for (int j = 0; j < 4; j++) {
                int c0 = (kh + 4 * j) ^ ((sr & 7) << 2);
                uint4 u = { to_tf32(bv[j].x), to_tf32(bv[j].y), to_tf32(bv[j].z), to_tf32(bv[j].w) };
                *(uint4*)&Bd[sr * 32 + c0] = u;
            }
        } else {
            #pragma unroll
            for (int it = 0; it < 4; it++) {
                int task = wid + 8 * it;
                int nb = (task & 3) << 5;
                int kq = (task >> 2) << 2;
                int n  = nb + lane;
                int c0 = kq ^ ((n & 7) << 2);
                uint4 u = { to_tf32(bv[it].x), to_tf32(bv[it].y), to_tf32(bv[it].z), to_tf32(bv[it].w) };
                *(uint4*)&Bd[n * 32 + c0] = u;
            }
        }
    };
    auto compute = [&](int buf) {
        const uint32_t* Ab = As[buf];
        const uint32_t* Bb = Bs[buf];
        #pragma unroll
        for (int ks = 0; ks < 4; ks++) {
            int c0 = ks * 8 + lc;
            uint32_t a[4][4], b[4][2];
            #pragma unroll
            for (int mt = 0; mt < 4; mt++) {
                const uint32_t* p = Ab + (wm * 64 + mt * 16 + lr) * 32;
                a[mt][0] = p[c0 ^ swz];
                a[mt][2] = p[(c0 + 4) ^ swz];
                p += 8 * 32;
                a[mt][1] = p[c0 ^ swz];
                a[mt][3] = p[(c0 + 4) ^ swz];
            }
            #pragma unroll
            for (int nt = 0; nt < 4; nt++) {
                const uint32_t* p = Bb + (wn * 32 + nt * 8 + lr) * 32;
                b[nt][0] = p[c0 ^ swz];
                b[nt][1] = p[(c0 + 4) ^ swz];
            }
            #pragma unroll
            for (int mt = 0; mt < 4; mt++)
                #pragma unroll
                for (int nt = 0; nt < 4; nt++)
                    mma_tf32(acc[mt][nt], a[mt], b[nt]);
        }
    };

    float4 av[4], bv[4];
    loadA(0, av); loadB(0, bv);
    stage(0, av, bv);
    __syncthreads();

    int ktiles = K >> 5;
    for (int kt = 0; kt < ktiles; kt++) {
        int buf = kt & 1;
        bool more = (kt + 1) < ktiles;
        if (more) { loadA(kt + 1, av); loadB(kt + 1, bv); }
        compute(buf);
        if (more) stage(buf ^ 1, av, bv);
        __syncthreads();
    }

    // epilogue
    #pragma unroll
    for (int mt = 0; mt < 4; mt++) {
        int r0 = by * 128 + wm * 64 + mt * 16 + lr;
        #pragma unroll
        for (int half = 0; half < 2; half++) {
            int r = r0 + 8 * half;
            float* crow = C + (size_t)r * ldc;
            #pragma unroll
            for (int nt = 0; nt < 4; nt++) {
                int cc = bx * 128 + wn * 32 + nt * 8 + 2 * lc;
                float2 v = make_float2(acc[mt][nt][2 * half], acc[mt][nt][2 * half + 1]);
                if (bias) {
                    float2 bb = *(const float2*)&bias[cc];
                    v.x += bb.x; v.y += bb.y;
                }
                if (flags & GF_GELU) {
                    v.x = 0.5f * v.x * (1.0f + erff(v.x * 0.70710678118654752f));
                    v.y = 0.5f * v.y * (1.0f + erff(v.y * 0.70710678118654752f));
                }
                if (flags & GF_ADDC) {
                    float2 o = *(const float2*)&crow[cc];
                    v.x += o.x; v.y += o.y;
                }
                *(float2*)&crow[cc] = v;
            }
        }
    }
}

// ---------------- host-side launcher -------------------------------------------------
static void launch_gemm(bool transB, const float* A, const float* B, float* C,
                        const float* bias, int M, int N, int K,
                        int lda, int ldb, int ldc,
                        long sAb, long sAh, long sBb, long sBh,
                        long sCb, long sCh, long sBiash,
                        int nB, int nH, int flags) {
    dim3 grid(N / 128, M / 128, nB * nH);
    if (transB)
        hmma_gemm<true><<<grid, 256, SMEM_REQ>>>(A, B, C, bias, M, N, K, lda, ldb, ldc,
                                                 sAb, sAh, sBb, sBh, sCb, sCh, sBiash, nH, flags);
    else
        hmma_gemm<false><<<grid, 256, SMEM_REQ>>>(A, B, C, bias, M, N, K, lda, ldb, ldc,
                                                  sAb, sAh, sBb, sBh, sCb, sCh, sBiash, nH, flags);
}

extern "C" void kernel_launch(void* const* d_in, const int* in_sizes, int n_in,
                              void* d_out, int out_size) {
    const int*   x         = (const int*)  d_in[0];
    const float* token_emb = (const float*)d_in[1];
    const float* Wq   = (const float*)d_in[2];
    const float* bq   = (const float*)d_in[3];
    const float* Wk   = (const float*)d_in[4];
    const float* bk   = (const float*)d_in[5];
    const float* Wv   = (const float*)d_in[6];
    const float* bv   = (const float*)d_in[7];
    const float* Wo   = (const float*)d_in[8];
    const float* bo   = (const float*)d_in[9];
    const float* ln1g = (const float*)d_in[10];
    const float* ln1b = (const float*)d_in[11];
    const float* ln2g = (const float*)d_in[12];
    const float* ln2b = (const float*)d_in[13];
    const float* W1   = (const float*)d_in[14];
    const float* b1   = (const float*)d_in[15];
    const float* W2   = (const float*)d_in[16];
    const float* b2   = (const float*)d_in[17];
    const float* flng = (const float*)d_in[18];
    const float* flnb = (const float*)d_in[19];
    const float* Wout = (const float*)d_in[20];
    float* out = (float*)d_out;

    cudaFuncSetAttribute(hmma_gemm<false>, cudaFuncAttributeMaxDynamicSharedMemorySize, SMEM_REQ);
    cudaFuncSetAttribute(hmma_gemm<true>,  cudaFuncAttributeMaxDynamicSharedMemorySize, SMEM_REQ);

    float *ph, *pxn, *pq, *pk, *pv, *ps, *py, *pff;
    cudaGetSymbolAddress((void**)&ph,  g_h);
    cudaGetSymbolAddress((void**)&pxn, g_xn);
    cudaGetSymbolAddress((void**)&pq,  g_q);
    cudaGetSymbolAddress((void**)&pk,  g_k);
    cudaGetSymbolAddress((void**)&pv,  g_v);
    cudaGetSymbolAddress((void**)&ps,  g_s);
    cudaGetSymbolAddress((void**)&py,  g_y);
    cudaGetSymbolAddress((void**)&pff, g_ff);

    embed_kernel<<<M_, 256>>>(x, token_emb, ph);

    for (int l = 0; l < L_; l++) {
        layernorm_kernel<<<M_, 256>>>(ph, pxn, ln1g + (size_t)l * D_, ln1b + (size_t)l * D_);

        const long wOff = (long)l * H_ * D_ * D_;
        const long bOff = (long)l * H_ * D_;
        launch_gemm(false, pxn, Wq + wOff, pq, bq + bOff,
                    M_, D_, D_, D_, D_, D_,
                    0, 0, 0, (long)D_ * D_, 0, (long)M_ * D_, D_, 1, H_, 0);
        launch_gemm(false, pxn, Wk + wOff, pk, bk + bOff,
                    M_, D_, D_, D_, D_, D_,
                    0, 0, 0, (long)D_ * D_, 0, (long)M_ * D_, D_, 1, H_, 0);
        launch_gemm(false, pxn, Wv + wOff, pv, bv + bOff,
                    M_, D_, D_, D_, D_, D_,
                    0, 0, 0, (long)D_ * D_, 0, (long)M_ * D_, D_, 1, H_, 0);

        // S = Q @ K^T per (b,h): B (K matrix) is [T,D] = [N,K] native layout
        launch_gemm(true, pq, pk, ps, nullptr,
                    T_, T_, D_, D_, D_, T_,
                    (long)T_ * D_, (long)M_ * D_,
                    (long)T_ * D_, (long)M_ * D_,
                    (long)H_ * T_ * T_, (long)T_ * T_,
                    0, B_, H_, GF_CAUSAL);

        attn_softmax_kernel<<<B_ * H_ * T_, 256>>>(ps);

        launch_gemm(false, ps, pv, py, nullptr,
                    T_, D_, T_, T_, D_, H_ * D_,
                    (long)H_ * T_ * T_, (long)T_ * T_,
                    (long)T_ * D_, (long)M_ * D_,
                    (long)T_ * H_ * D_, (long)D_,
                    0, B_, H_, GF_KLIM);

        launch_gemm(false, py, Wo + (long)l * H_ * D_ * D_, ph, bo + (long)l * D_,
                    M_, D_, H_ * D_, H_ * D_, D_, D_,
                    0, 0, 0, 0, 0, 0, 0, 1, 1, GF_ADDC);

        layernorm_kernel<<<M_, 256>>>(ph, pxn, ln2g + (size_t)l * D_, ln2b + (size_t)l * D_);

        launch_gemm(false, pxn, W1 + (long)l * D_ * DFF_, pff, b1 + (long)l * DFF_,
                    M_, DFF_, D_, D_, DFF_, DFF_,
                    0, 0, 0, 0, 0, 0, 0, 1, 1, GF_GELU);

        launch_gemm(false, pff, W2 + (long)l * DFF_ * D_, ph, b2 + (long)l * D_,
                    M_, D_, DFF_, DFF_, D_, D_,
                    0, 0, 0, 0, 0, 0, 0, 1, 1, GF_ADDC);
    }

    layernorm_kernel<<<M_, 256>>>(ph, pxn, flng, flnb);

    launch_gemm(false, pxn, Wout, out, nullptr,
                M_, V_, D_, D_, V_, V_,
                0, 0, 0, 0, 0, 0, 0, 1, 1, 0);

    logsoftmax_kernel<<<M_, 256>>>(out);
}

// round 5
// speedup vs baseline: 3.6809x; 1.9968x over previous
#include <cuda_runtime.h>
#include <cstdint>
#include <math.h>

#define L_   4
#define H_   4
#define B_   2
#define T_   1024
#define D_   1024
#define DFF_ 4096
#define V_   32000
#define M_   (B_*T_)   // 2048 tokens

// ---------------- scratch (static device globals; no allocs allowed) ----------
__device__ float g_h [M_*D_];
__device__ float g_xn[M_*D_];
__device__ float g_q [H_*M_*D_];
__device__ float g_k [H_*M_*D_];
__device__ float g_v [H_*M_*D_];
__device__ float g_s [B_*H_*T_*T_];
__device__ float g_y [M_*H_*D_];
__device__ float g_ff[M_*DFF_];

// ---------------- helpers -------------------------------------------------------
__device__ __forceinline__ uint32_t smem_u32(const void* p) {
    uint32_t a;
    asm("{ .reg .u64 t; cvta.to.shared.u64 t, %1; cvt.u32.u64 %0, t; }" : "=r"(a) : "l"(p));
    return a;
}
__device__ __forceinline__ void cpa16(uint32_t dst, const void* src) {
    asm volatile("cp.async.cg.shared.global [%0], [%1], 16;" :: "r"(dst), "l"(src) : "memory");
}
#define CP_COMMIT() asm volatile("cp.async.commit_group;" ::: "memory")
#define CP_WAIT(n)  asm volatile("cp.async.wait_group %0;" :: "n"(n) : "memory")

__device__ __forceinline__ void mma_tf32(float* c, const uint32_t* a, const uint32_t* b) {
    asm volatile("mma.sync.aligned.m16n8k8.row.col.f32.tf32.tf32.f32 "
        "{%0,%1,%2,%3}, {%4,%5,%6,%7}, {%8,%9}, {%0,%1,%2,%3};"
        : "+f"(c[0]), "+f"(c[1]), "+f"(c[2]), "+f"(c[3])
        : "r"(a[0]), "r"(a[1]), "r"(a[2]), "r"(a[3]), "r"(b[0]), "r"(b[1]));
}

// ---------------- fast exp on the FMA pipe --------------------------------------
__device__ __forceinline__ float fexp(float x) {
    x = fmaxf(x, -80.f);
    float z = x * 1.4426950408889634f;
    float y = z + 12582912.0f;
    float n = y - 12582912.0f;
    float t = fmaf(n, -0.6931471805599453f, x);
    float p =             0.008333333f;
    p = fmaf(p, t, 0.041666668f);
    p = fmaf(p, t, 0.16666667f);
    p = fmaf(p, t, 0.5f);
    p = fmaf(p, t, 1.0f);
    p = fmaf(p, t, 1.0f);
    int e = __float_as_int(y) - 0x4B400000;
    return p * __int_as_float((127 + e) << 23);
}

// ---------------- block reductions ----------------------------------------------
__device__ __forceinline__ float blockReduceSum(float v) {
    __shared__ float sh[9];
    int lane = threadIdx.x & 31, w = threadIdx.x >> 5;
    #pragma unroll
    for (int o = 16; o; o >>= 1) v += __shfl_xor_sync(0xffffffffu, v, o);
    if (lane == 0) sh[w] = v;
    __syncthreads();
    if (threadIdx.x == 0) {
        float s = 0.f;
        #pragma unroll
        for (int i = 0; i < 8; i++) s += sh[i];
        sh[8] = s;
    }
    __syncthreads();
    float r = sh[8];
    __syncthreads();
    return r;
}
__device__ __forceinline__ float blockReduceMax(float v) {
    __shared__ float sh[9];
    int lane = threadIdx.x & 31, w = threadIdx.x >> 5;
    #pragma unroll
    for (int o = 16; o; o >>= 1) v = fmaxf(v, __shfl_xor_sync(0xffffffffu, v, o));
    if (lane == 0) sh[w] = v;
    __syncthreads();
    if (threadIdx.x == 0) {
        float s = sh[0];
        #pragma unroll
        for (int i = 1; i < 8; i++) s = fmaxf(s, sh[i]);
        sh[8] = s;
    }
    __syncthreads();
    float r = sh[8];
    __syncthreads();
    return r;
}

// ---------------- embedding ------------------------------------------------------
__global__ void embed_kernel(const int* __restrict__ x,
                             const float* __restrict__ emb,
                             float* __restrict__ h) {
    int m = blockIdx.x;
    int t = m % T_;
    int tok = x[m];
    const float* erow = emb + (size_t)tok * D_;
    float* hrow = h + (size_t)m * D_;
    for (int d = threadIdx.x; d < D_; d += blockDim.x) {
        int i = d >> 1;
        float denom = powf(10000.f, (2.f * (float)i) / (float)D_);
        float ang = (float)t / denom;
        float pe = (d & 1) ? cosf(ang) : sinf(ang);
        hrow[d] = erow[d] + pe;
    }
}

// ---------------- layernorm -------------------------------------------------------
__global__ void layernorm_kernel(const float* __restrict__ in,
                                 float* __restrict__ out,
                                 const float* __restrict__ g,
                                 const float* __restrict__ b) {
    int m = blockIdx.x;
    int tid = threadIdx.x;
    const float4* x4 = (const float4*)(in + (size_t)m * D_);
    float4 v = x4[tid];
    float s = v.x + v.y + v.z + v.w;
    s = blockReduceSum(s);
    float mean = s * (1.0f / D_);
    float dx = v.x - mean, dy = v.y - mean, dz = v.z - mean, dw = v.w - mean;
    float q = dx*dx + dy*dy + dz*dz + dw*dw;
    q = blockReduceSum(q);
    float inv = rsqrtf(q * (1.0f / D_) + 1e-5f);
    float4 gg = ((const float4*)g)[tid];
    float4 bb = ((const float4*)b)[tid];
    float4 o;
    o.x = dx * inv * gg.x + bb.x;
    o.y = dy * inv * gg.y + bb.y;
    o.z = dz * inv * gg.z + bb.z;
    o.w = dw * inv * gg.w + bb.w;
    ((float4*)(out + (size_t)m * D_))[tid] = o;
}

// ---------------- causal softmax ---------------------------------------------------
__global__ void attn_softmax_kernel(float* __restrict__ S) {
    int r = blockIdx.x;            // 0 .. B*H*T-1
    int t = r % T_;
    int z = r / T_;
    float* row = S + (size_t)z * T_ * T_ + (size_t)t * T_;
    const float scale = 0.03125f;  // 1/sqrt(1024)
    int tid = threadIdx.x;
    float v[4];
    #pragma unroll
    for (int i = 0; i < 4; i++) {
        int s = tid + 256 * i;
        v[i] = (s <= t) ? row[s] * scale : -INFINITY;
    }
    float lmax = fmaxf(fmaxf(v[0], v[1]), fmaxf(v[2], v[3]));
    float mx = blockReduceMax(lmax);
    float e[4]; float lsum = 0.f;
    #pragma unroll
    for (int i = 0; i < 4; i++) {
        int s = tid + 256 * i;
        e[i] = (s <= t) ? fexp(v[i] - mx) : 0.f;
        lsum += e[i];
    }
    float sum = blockReduceSum(lsum);
    float invs = 1.0f / sum;
    #pragma unroll
    for (int i = 0; i < 4; i++) {
        int s = tid + 256 * i;
        row[s] = e[i] * invs;
    }
}

// ---------------- final log-softmax -------------------------------------------------
__global__ void logsoftmax_kernel(float* __restrict__ out) {
    float* row = out + (size_t)blockIdx.x * V_;
    int tid = threadIdx.x;
    float lmax = -INFINITY;
    for (int i = tid; i < V_; i += 256) lmax = fmaxf(lmax, row[i]);
    float mx = blockReduceMax(lmax);
    float lsum = 0.f;
    for (int i = tid; i < V_; i += 256) lsum += fexp(row[i] - mx);
    float sum = blockReduceSum(lsum);
    float lse = logf(sum) + mx;
    for (int i = tid; i < V_; i += 256) row[i] -= lse;
}

// ---------------- HMMA tf32 batched GEMM, cp.async pipeline --------------------------
// C = [residual +] act( A @ B(^T) + bias ), batch z = zb*nH+zh
// CTA 128x128, K-tile 32, 8 warps (2m x 4n), warp 64x32 via m16n8k8 tf32 HMMA.
// A (and B when TRANSB): SMEM [row][32] fp32 bits, XOR swizzle c ^= (row&7)<<2.
// B when !TRANSB: natural [k][136] padded rows (no transpose, conflict-free frags).
// fp32 operands fed to tf32 MMA raw: HW uses bits[31:13] (truncation).
#define GF_ADDC   1
#define GF_GELU   2
#define GF_CAUSAL 4
#define GF_KLIM   8

#define A_BYTES   16384                 // 128 x 32 x 4
#define BN_BYTES  17408                 // 32 x 136 x 4  (covers TRANSB's 16384 too)
#define STAGE     (A_BYTES + BN_BYTES)  // 33792
#define SMEM_REQ  (2 * STAGE)           // 67584

template<bool TRANSB>
__global__ void __launch_bounds__(256, 2)
hmma_gemm(const float* __restrict__ A, const float* __restrict__ B,
          float* __restrict__ C, const float* __restrict__ bias,
          int M, int N, int K, int lda, int ldb, int ldc,
          long sAb, long sAh, long sBb, long sBh, long sCb, long sCh,
          long sBiash, int nH, int flags) {
    int bx = blockIdx.x, by = blockIdx.y;
    if ((flags & GF_CAUSAL) && bx > by) return;
    if (flags & GF_KLIM) K = min(K, (by + 1) * 128);

    extern __shared__ char sm[];
    uint32_t smA[2] = { smem_u32(sm),             smem_u32(sm + STAGE) };
    uint32_t smB[2] = { smA[0] + A_BYTES,         smA[1] + A_BYTES };

    int z  = blockIdx.z;
    int zb = z / nH, zh = z % nH;
    A += (size_t)zb * sAb + (size_t)zh * sAh;
    B += (size_t)zb * sBb + (size_t)zh * sBh;
    C += (size_t)zb * sCb + (size_t)zh * sCh;
    if (bias) bias += (size_t)zh * sBiash;

    const int tid = threadIdx.x;
    const int wid = tid >> 5, lane = tid & 31;
    const int lr = lane >> 2, lc = lane & 3;
    const int wm = wid & 1, wn = wid >> 1;      // warp tile: rows wm*64, cols wn*32
    const int swz = lr << 2;

    // A staging: thread -> row tid>>1, 16B chunks (tid&1)*4 + j (j=0..3), swizzled
    const int sr  = tid >> 1;
    const int sc4 = (tid & 1) << 2;             // base 16B-chunk index
    const float* Arow = A + (size_t)(by * 128 + sr) * lda;
    const float* Brow = TRANSB ? (B + (size_t)(bx * 128 + sr) * ldb) : nullptr;
    // !TRANSB staging: thread -> k = tid>>3, chunks (tid&7) + 8j
    const int bk  = tid >> 3;
    const int bc  = tid & 7;
    const float* Bk = TRANSB ? nullptr : (B + (size_t)bk * ldb + (size_t)bx * 128);

    auto issue = [&](int kt, int s) {
        const float* a = Arow + kt * 32;
        #pragma unroll
        for (int j = 0; j < 4; j++) {
            int c0 = (sc4 + j) << 2;                       // float col
            int scol = c0 ^ ((sr & 7) << 2);
            cpa16(smA[s] + (uint32_t)(sr * 128 + scol * 4), a + c0);
        }
        if (TRANSB) {
            const float* b = Brow + kt * 32;
            #pragma unroll
            for (int j = 0; j < 4; j++) {
                int c0 = (sc4 + j) << 2;
                int scol = c0 ^ ((sr & 7) << 2);
                cpa16(smB[s] + (uint32_t)(sr * 128 + scol * 4), b + c0);
            }
        } else {
            const float* b = Bk + (size_t)kt * 32 * ldb;
            #pragma unroll
            for (int j = 0; j < 4; j++) {
                int ch = bc + 8 * j;                       // 16B chunk in row (0..31)
                cpa16(smB[s] + (uint32_t)(bk * 544 + ch * 16), b + ch * 4);
            }
        }
        CP_COMMIT();
    };

    float acc[4][4][4];
    #pragma unroll
    for (int i = 0; i < 4; i++)
        #pragma unroll
        for (int j = 0; j < 4; j++)
            #pragma unroll
            for (int q = 0; q < 4; q++) acc[i][j][q] = 0.f;

    auto compute = [&](int s) {
        const uint32_t* Ab = (const uint32_t*)(sm + (s ? STAGE : 0));
        const uint32_t* Bb = Ab + (A_BYTES / 4);
        #pragma unroll
        for (int ks = 0; ks < 4; ks++) {
            int c0 = ks * 8 + lc;
            uint32_t a[4][4], b[4][2];
            #pragma unroll
            for (int mt = 0; mt < 4; mt++) {
                const uint32_t* p = Ab + (wm * 64 + mt * 16 + lr) * 32;
                a[mt][0] = p[c0 ^ swz];
                a[mt][2] = p[(c0 + 4) ^ swz];
                p += 8 * 32;
                a[mt][1] = p[c0 ^ swz];
                a[mt][3] = p[(c0 + 4) ^ swz];
            }
            if (TRANSB) {
                #pragma unroll
                for (int nt = 0; nt < 4; nt++) {
                    const uint32_t* p = Bb + (wn * 32 + nt * 8 + lr) * 32;
                    b[nt][0] = p[c0 ^ swz];
                    b[nt][1] = p[(c0 + 4) ^ swz];
                }
            } else {
                int n0 = wn * 32 + lr;
                #pragma unroll
                for (int nt = 0; nt < 4; nt++) {
                    b[nt][0] = Bb[(ks * 8 + lc) * 136 + n0 + nt * 8];
                    b[nt][1] = Bb[(ks * 8 + lc + 4) * 136 + n0 + nt * 8];
                }
            }
            #pragma unroll
            for (int mt = 0; mt < 4; mt++)
                #pragma unroll
                for (int nt = 0; nt < 4; nt++)
                    mma_tf32(acc[mt][nt], a[mt], b[nt]);
        }
    };

    int ktiles = K >> 5;              // >= 4 always
    issue(0, 0);
    issue(1, 1);

    for (int kt = 0; kt < ktiles; kt++) {
        int buf = kt & 1;
        if (kt + 1 < ktiles) { CP_WAIT(1); } else { CP_WAIT(0); }
        __syncthreads();
        compute(buf);
        __syncthreads();
        if (kt + 2 < ktiles) issue(kt + 2, buf);
    }

    // epilogue
    #pragma unroll
    for (int mt = 0; mt < 4; mt++) {
        int r0 = by * 128 + wm * 64 + mt * 16 + lr;
        #pragma unroll
        for (int half = 0; half < 2; half++) {
            int r = r0 + 8 * half;
            float* crow = C + (size_t)r * ldc;
            #pragma unroll
            for (int nt = 0; nt < 4; nt++) {
                int cc = bx * 128 + wn * 32 + nt * 8 + 2 * lc;
                float2 v = make_float2(acc[mt][nt][2 * half], acc[mt][nt][2 * half + 1]);
                if (bias) {
                    float2 bb = *(const float2*)&bias[cc];
                    v.x += bb.x; v.y += bb.y;
                }
                if (flags & GF_GELU) {
                    v.x = 0.5f * v.x * (1.0f + erff(v.x * 0.70710678118654752f));
                    v.y = 0.5f * v.y * (1.0f + erff(v.y * 0.70710678118654752f));
                }
                if (flags & GF_ADDC) {
                    float2 o = *(const float2*)&crow[cc];
                    v.x += o.x; v.y += o.y;
                }
                *(float2*)&crow[cc] = v;
            }
        }
    }
}

// ---------------- host-side launcher -------------------------------------------------
static void launch_gemm(bool transB, const float* A, const float* B, float* C,
                        const float* bias, int M, int N, int K,
                        int lda, int ldb, int ldc,
                        long sAb, long sAh, long sBb, long sBh,
                        long sCb, long sCh, long sBiash,
                        int nB, int nH, int flags) {
    dim3 grid(N / 128, M / 128, nB * nH);
    if (transB)
        hmma_gemm<true><<<grid, 256, SMEM_REQ>>>(A, B, C, bias, M, N, K, lda, ldb, ldc,
                                                 sAb, sAh, sBb, sBh, sCb, sCh, sBiash, nH, flags);
    else
        hmma_gemm<false><<<grid, 256, SMEM_REQ>>>(A, B, C, bias, M, N, K, lda, ldb, ldc,
                                                  sAb, sAh, sBb, sBh, sCb, sCh, sBiash, nH, flags);
}

extern "C" void kernel_launch(void* const* d_in, const int* in_sizes, int n_in,
                              void* d_out, int out_size) {
    const int*   x         = (const int*)  d_in[0];
    const float* token_emb = (const float*)d_in[1];
    const float* Wq   = (const float*)d_in[2];
    const float* bq   = (const float*)d_in[3];
    const float* Wk   = (const float*)d_in[4];
    const float* bk   = (const float*)d_in[5];
    const float* Wv   = (const float*)d_in[6];
    const float* bv   = (const float*)d_in[7];
    const float* Wo   = (const float*)d_in[8];
    const float* bo   = (const float*)d_in[9];
    const float* ln1g = (const float*)d_in[10];
    const float* ln1b = (const float*)d_in[11];
    const float* ln2g = (const float*)d_in[12];
    const float* ln2b = (const float*)d_in[13];
    const float* W1   = (const float*)d_in[14];
    const float* b1   = (const float*)d_in[15];
    const float* W2   = (const float*)d_in[16];
    const float* b2   = (const float*)d_in[17];
    const float* flng = (const float*)d_in[18];
    const float* flnb = (const float*)d_in[19];
    const float* Wout = (const float*)d_in[20];
    float* out = (float*)d_out;

    cudaFuncSetAttribute(hmma_gemm<false>, cudaFuncAttributeMaxDynamicSharedMemorySize, SMEM_REQ);
    cudaFuncSetAttribute(hmma_gemm<true>,  cudaFuncAttributeMaxDynamicSharedMemorySize, SMEM_REQ);

    float *ph, *pxn, *pq, *pk, *pv, *ps, *py, *pff;
    cudaGetSymbolAddress((void**)&ph,  g_h);
    cudaGetSymbolAddress((void**)&pxn, g_xn);
    cudaGetSymbolAddress((void**)&pq,  g_q);
    cudaGetSymbolAddress((void**)&pk,  g_k);
    cudaGetSymbolAddress((void**)&pv,  g_v);
    cudaGetSymbolAddress((void**)&ps,  g_s);
    cudaGetSymbolAddress((void**)&py,  g_y);
    cudaGetSymbolAddress((void**)&pff, g_ff);

    embed_kernel<<<M_, 256>>>(x, token_emb, ph);

    for (int l = 0; l < L_; l++) {
        layernorm_kernel<<<M_, 256>>>(ph, pxn, ln1g + (size_t)l * D_, ln1b + (size_t)l * D_);

        const long wOff = (long)l * H_ * D_ * D_;
        const long bOff = (long)l * H_ * D_;
        launch_gemm(false, pxn, Wq + wOff, pq, bq + bOff,
                    M_, D_, D_, D_, D_, D_,
                    0, 0, 0, (long)D_ * D_, 0, (long)M_ * D_, D_, 1, H_, 0);
        launch_gemm(false, pxn, Wk + wOff, pk, bk + bOff,
                    M_, D_, D_, D_, D_, D_,
                    0, 0, 0, (long)D_ * D_, 0, (long)M_ * D_, D_, 1, H_, 0);
        launch_gemm(false, pxn, Wv + wOff, pv, bv + bOff,
                    M_, D_, D_, D_, D_, D_,
                    0, 0, 0, (long)D_ * D_, 0, (long)M_ * D_, D_, 1, H_, 0);

        // S = Q @ K^T per (b,h): B (K matrix) is [T,D] = [N,K] native layout
        launch_gemm(true, pq, pk, ps, nullptr,
                    T_, T_, D_, D_, D_, T_,
                    (long)T_ * D_, (long)M_ * D_,
                    (long)T_ * D_, (long)M_ * D_,
                    (long)H_ * T_ * T_, (long)T_ * T_,
                    0, B_, H_, GF_CAUSAL);

        attn_softmax_kernel<<<B_ * H_ * T_, 256>>>(ps);

        launch_gemm(false, ps, pv, py, nullptr,
                    T_, D_, T_, T_, D_, H_ * D_,
                    (long)H_ * T_ * T_, (long)T_ * T_,
                    (long)T_ * D_, (long)M_ * D_,
                    (long)T_ * H_ * D_, (long)D_,
                    0, B_, H_, GF_KLIM);

        launch_gemm(false, py, Wo + (long)l * H_ * D_ * D_, ph, bo + (long)l * D_,
                    M_, D_, H_ * D_, H_ * D_, D_, D_,
                    0, 0, 0, 0, 0, 0, 0, 1, 1, GF_ADDC);

        layernorm_kernel<<<M_, 256>>>(ph, pxn, ln2g + (size_t)l * D_, ln2b + (size_t)l * D_);

        launch_gemm(false, pxn, W1 + (long)l * D_ * DFF_, pff, b1 + (long)l * DFF_,
                    M_, DFF_, D_, D_, DFF_, DFF_,
                    0, 0, 0, 0, 0, 0, 0, 1, 1, GF_GELU);

        launch_gemm(false, pff, W2 + (long)l * DFF_ * D_, ph, b2 + (long)l * D_,
                    M_, D_, DFF_, DFF_, D_, D_,
                    0, 0, 0, 0, 0, 0, 0, 1, 1, GF_ADDC);
    }

    layernorm_kernel<<<M_, 256>>>(ph, pxn, flng, flnb);

    launch_gemm(false, pxn, Wout, out, nullptr,
                M_, V_, D_, D_, V_, V_,
                0, 0, 0, 0, 0, 0, 0, 1, 1, 0);

    logsoftmax_kernel<<<M_, 256>>>(out);
}

// round 6
// speedup vs baseline: 4.1545x; 1.1287x over previous
#include <cuda_runtime.h>
#include <cstdint>
#include <math.h>

#define L_   4
#define H_   4
#define B_   2
#define T_   1024
#define D_   1024
#define DFF_ 4096
#define V_   32000
#define M_   (B_*T_)   // 2048 tokens

// ---------------- scratch (static device globals; no allocs allowed) ----------
__device__ float g_h [M_*D_];
__device__ float g_xn[M_*D_];
__device__ float g_q [H_*M_*D_];
__device__ float g_k [H_*M_*D_];
__device__ float g_v [H_*M_*D_];
__device__ float g_s [B_*H_*T_*T_];
__device__ float g_y [M_*H_*D_];
__device__ float g_ff[M_*DFF_];

// ---------------- helpers -------------------------------------------------------
__device__ __forceinline__ uint32_t smem_u32(const void* p) {
    uint32_t a;
    asm("{ .reg .u64 t; cvta.to.shared.u64 t, %1; cvt.u32.u64 %0, t; }" : "=r"(a) : "l"(p));
    return a;
}
__device__ __forceinline__ void cpa16(uint32_t dst, const void* src) {
    asm volatile("cp.async.cg.shared.global [%0], [%1], 16;" :: "r"(dst), "l"(src) : "memory");
}
#define CP_COMMIT() asm volatile("cp.async.commit_group;" ::: "memory")
#define CP_WAIT(n)  asm volatile("cp.async.wait_group %0;" :: "n"(n) : "memory")

__device__ __forceinline__ void mma_tf32(float* c, const uint32_t* a, const uint32_t* b) {
    asm volatile("mma.sync.aligned.m16n8k8.row.col.f32.tf32.tf32.f32 "
        "{%0,%1,%2,%3}, {%4,%5,%6,%7}, {%8,%9}, {%0,%1,%2,%3};"
        : "+f"(c[0]), "+f"(c[1]), "+f"(c[2]), "+f"(c[3])
        : "r"(a[0]), "r"(a[1]), "r"(a[2]), "r"(a[3]), "r"(b[0]), "r"(b[1]));
}

// ---------------- fast exp on the FMA pipe --------------------------------------
__device__ __forceinline__ float fexp(float x) {
    x = fmaxf(x, -80.f);
    float z = x * 1.4426950408889634f;
    float y = z + 12582912.0f;
    float n = y - 12582912.0f;
    float t = fmaf(n, -0.6931471805599453f, x);
    float p =             0.008333333f;
    p = fmaf(p, t, 0.041666668f);
    p = fmaf(p, t, 0.16666667f);
    p = fmaf(p, t, 0.5f);
    p = fmaf(p, t, 1.0f);
    p = fmaf(p, t, 1.0f);
    int e = __float_as_int(y) - 0x4B400000;
    return p * __int_as_float((127 + e) << 23);
}

// ---------------- block reductions ----------------------------------------------
__device__ __forceinline__ float blockReduceSum(float v) {
    __shared__ float sh[9];
    int lane = threadIdx.x & 31, w = threadIdx.x >> 5;
    #pragma unroll
    for (int o = 16; o; o >>= 1) v += __shfl_xor_sync(0xffffffffu, v, o);
    if (lane == 0) sh[w] = v;
    __syncthreads();
    if (threadIdx.x == 0) {
        float s = 0.f;
        #pragma unroll
        for (int i = 0; i < 8; i++) s += sh[i];
        sh[8] = s;
    }
    __syncthreads();
    float r = sh[8];
    __syncthreads();
    return r;
}
__device__ __forceinline__ float blockReduceMax(float v) {
    __shared__ float sh[9];
    int lane = threadIdx.x & 31, w = threadIdx.x >> 5;
    #pragma unroll
    for (int o = 16; o; o >>= 1) v = fmaxf(v, __shfl_xor_sync(0xffffffffu, v, o));
    if (lane == 0) sh[w] = v;
    __syncthreads();
    if (threadIdx.x == 0) {
        float s = sh[0];
        #pragma unroll
        for (int i = 1; i < 8; i++) s = fmaxf(s, sh[i]);
        sh[8] = s;
    }
    __syncthreads();
    float r = sh[8];
    __syncthreads();
    return r;
}

// ---------------- embedding ------------------------------------------------------
__global__ void embed_kernel(const int* __restrict__ x,
                             const float* __restrict__ emb,
                             float* __restrict__ h) {
    int m = blockIdx.x;
    int t = m % T_;
    int tok = x[m];
    const float* erow = emb + (size_t)tok * D_;
    float* hrow = h + (size_t)m * D_;
    for (int d = threadIdx.x; d < D_; d += blockDim.x) {
        int i = d >> 1;
        float denom = powf(10000.f, (2.f * (float)i) / (float)D_);
        float ang = (float)t / denom;
        float pe = (d & 1) ? cosf(ang) : sinf(ang);
        hrow[d] = erow[d] + pe;
    }
}

// ---------------- layernorm -------------------------------------------------------
__global__ void layernorm_kernel(const float* __restrict__ in,
                                 float* __restrict__ out,
                                 const float* __restrict__ g,
                                 const float* __restrict__ b) {
    int m = blockIdx.x;
    int tid = threadIdx.x;
    const float4* x4 = (const float4*)(in + (size_t)m * D_);
    float4 v = x4[tid];
    float s = v.x + v.y + v.z + v.w;
    s = blockReduceSum(s);
    float mean = s * (1.0f / D_);
    float dx = v.x - mean, dy = v.y - mean, dz = v.z - mean, dw = v.w - mean;
    float q = dx*dx + dy*dy + dz*dz + dw*dw;
    q = blockReduceSum(q);
    float inv = rsqrtf(q * (1.0f / D_) + 1e-5f);
    float4 gg = ((const float4*)g)[tid];
    float4 bb = ((const float4*)b)[tid];
    float4 o;
    o.x = dx * inv * gg.x + bb.x;
    o.y = dy * inv * gg.y + bb.y;
    o.z = dz * inv * gg.z + bb.z;
    o.w = dw * inv * gg.w + bb.w;
    ((float4*)(out + (size_t)m * D_))[tid] = o;
}

// ---------------- causal softmax ---------------------------------------------------
__global__ void attn_softmax_kernel(float* __restrict__ S) {
    int r = blockIdx.x;            // 0 .. B*H*T-1
    int t = r % T_;
    int z = r / T_;
    float* row = S + (size_t)z * T_ * T_ + (size_t)t * T_;
    const float scale = 0.03125f;  // 1/sqrt(1024)
    int tid = threadIdx.x;
    float v[4];
    #pragma unroll
    for (int i = 0; i < 4; i++) {
        int s = tid + 256 * i;
        v[i] = (s <= t) ? row[s] * scale : -INFINITY;
    }
    float lmax = fmaxf(fmaxf(v[0], v[1]), fmaxf(v[2], v[3]));
    float mx = blockReduceMax(lmax);
    float e[4]; float lsum = 0.f;
    #pragma unroll
    for (int i = 0; i < 4; i++) {
        int s = tid + 256 * i;
        e[i] = (s <= t) ? fexp(v[i] - mx) : 0.f;
        lsum += e[i];
    }
    float sum = blockReduceSum(lsum);
    float invs = 1.0f / sum;
    #pragma unroll
    for (int i = 0; i < 4; i++) {
        int s = tid + 256 * i;
        row[s] = e[i] * invs;
    }
}

// ---------------- final log-softmax -------------------------------------------------
__global__ void logsoftmax_kernel(float* __restrict__ out) {
    float* row = out + (size_t)blockIdx.x * V_;
    int tid = threadIdx.x;
    float lmax = -INFINITY;
    for (int i = tid; i < V_; i += 256) lmax = fmaxf(lmax, row[i]);
    float mx = blockReduceMax(lmax);
    float lsum = 0.f;
    for (int i = tid; i < V_; i += 256) lsum += fexp(row[i] - mx);
    float sum = blockReduceSum(lsum);
    float lse = logf(sum) + mx;
    for (int i = tid; i < V_; i += 256) row[i] -= lse;
}

// ---------------- HMMA tf32 GEMM body: 3-stage cp.async, 1 sync per k-tile ---------
// CTA 128x128, K-tile 32, 8 warps (2m x 4n), warp 64x32 via m16n8k8 tf32 HMMA.
// A (and B when TRANSB): SMEM [row][32] fp32 bits, XOR swizzle c ^= (row&7)<<2.
// B when !TRANSB: natural [k][136] padded rows (no transpose, conflict-free frags).
// fp32 operands fed to tf32 MMA raw (bits[31:13] truncation).
#define GF_ADDC   1
#define GF_GELU   2

#define A_BYTES   16384                 // 128 x 32 x 4
#define BN_BYTES  17408                 // 32 x 136 x 4  (covers TRANSB's 16384 too)
#define STAGE     (A_BYTES + BN_BYTES)  // 33792
#define NSTAGE    3
#define SMEM_REQ  (NSTAGE * STAGE)      // 101376

template<bool TRANSB>
__device__ __forceinline__ void gemm_body(
        const float* __restrict__ A, const float* __restrict__ B,
        float* __restrict__ C, const float* __restrict__ bias,
        int K, int lda, int ldb, int ldc, int bx, int by, int flags) {
    extern __shared__ char sm[];
    const uint32_t smBase = smem_u32(sm);

    const int tid = threadIdx.x;
    const int wid = tid >> 5, lane = tid & 31;
    const int lr = lane >> 2, lc = lane & 3;
    const int wm = wid & 1, wn = wid >> 1;      // warp tile: rows wm*64, cols wn*32
    const int swz = lr << 2;

    // A staging: thread -> row tid>>1, 16B chunks (tid&1)*4 + j (j=0..3), swizzled
    const int sr  = tid >> 1;
    const int sc4 = (tid & 1) << 2;
    const float* Arow = A + (size_t)(by * 128 + sr) * lda;
    const float* Brow = TRANSB ? (B + (size_t)(bx * 128 + sr) * ldb) : nullptr;
    const int bk  = tid >> 3;
    const int bc  = tid & 7;
    const float* Bk = TRANSB ? nullptr : (B + (size_t)bk * ldb + (size_t)bx * 128);

    auto issue = [&](int kt, int s) {
        uint32_t dA = smBase + s * STAGE;
        uint32_t dB = dA + A_BYTES;
        const float* a = Arow + kt * 32;
        #pragma unroll
        for (int j = 0; j < 4; j++) {
            int c0 = (sc4 + j) << 2;
            int scol = c0 ^ ((sr & 7) << 2);
            cpa16(dA + (uint32_t)(sr * 128 + scol * 4), a + c0);
        }
        if (TRANSB) {
            const float* b = Brow + kt * 32;
            #pragma unroll
            for (int j = 0; j < 4; j++) {
                int c0 = (sc4 + j) << 2;
                int scol = c0 ^ ((sr & 7) << 2);
                cpa16(dB + (uint32_t)(sr * 128 + scol * 4), b + c0);
            }
        } else {
            const float* b = Bk + (size_t)kt * 32 * ldb;
            #pragma unroll
            for (int j = 0; j < 4; j++) {
                int ch = bc + 8 * j;
                cpa16(dB + (uint32_t)(bk * 544 + ch * 16), b + ch * 4);
            }
        }
        CP_COMMIT();
    };

    float acc[4][4][4];
    #pragma unroll
    for (int i = 0; i < 4; i++)
        #pragma unroll
        for (int j = 0; j < 4; j++)
            #pragma unroll
            for (int q = 0; q < 4; q++) acc[i][j][q] = 0.f;

    auto compute = [&](int s) {
        const uint32_t* Ab = (const uint32_t*)(sm + s * STAGE);
        const uint32_t* Bb = Ab + (A_BYTES / 4);
        #pragma unroll
        for (int ks = 0; ks < 4; ks++) {
            int c0 = ks * 8 + lc;
            uint32_t a[4][4], b[4][2];
            #pragma unroll
            for (int mt = 0; mt < 4; mt++) {
                const uint32_t* p = Ab + (wm * 64 + mt * 16 + lr) * 32;
                a[mt][0] = p[c0 ^ swz];
                a[mt][2] = p[(c0 + 4) ^ swz];
                p += 8 * 32;
                a[mt][1] = p[c0 ^ swz];
                a[mt][3] = p[(c0 + 4) ^ swz];
            }
            if (TRANSB) {
                #pragma unroll
                for (int nt = 0; nt < 4; nt++) {
                    const uint32_t* p = Bb + (wn * 32 + nt * 8 + lr) * 32;
                    b[nt][0] = p[c0 ^ swz];
                    b[nt][1] = p[(c0 + 4) ^ swz];
                }
            } else {
                int n0 = wn * 32 + lr;
                #pragma unroll
                for (int nt = 0; nt < 4; nt++) {
                    b[nt][0] = Bb[(ks * 8 + lc) * 136 + n0 + nt * 8];
                    b[nt][1] = Bb[(ks * 8 + lc + 4) * 136 + n0 + nt * 8];
                }
            }
            #pragma unroll
            for (int mt = 0; mt < 4; mt++)
                #pragma unroll
                for (int nt = 0; nt < 4; nt++)
                    mma_tf32(acc[mt][nt], a[mt], b[nt]);
        }
    };

    int ktiles = K >> 5;               // always >= 4 here
    issue(0, 0);
    issue(1, 1);

    for (int kt = 0; kt < ktiles; kt++) {
        int buf = kt % NSTAGE;
        if (kt + 1 < ktiles) { CP_WAIT(1); } else { CP_WAIT(0); }
        __syncthreads();
        compute(buf);
        if (kt + 2 < ktiles) issue(kt + 2, (kt + 2) % NSTAGE);
    }

    // epilogue
    #pragma unroll
    for (int mt = 0; mt < 4; mt++) {
        int r0 = by * 128 + wm * 64 + mt * 16 + lr;
        #pragma unroll
        for (int half = 0; half < 2; half++) {
            int r = r0 + 8 * half;
            float* crow = C + (size_t)r * ldc;
            #pragma unroll
            for (int nt = 0; nt < 4; nt++) {
                int cc = bx * 128 + wn * 32 + nt * 8 + 2 * lc;
                float2 v = make_float2(acc[mt][nt][2 * half], acc[mt][nt][2 * half + 1]);
                if (bias) {
                    float2 bb = *(const float2*)&bias[cc];
                    v.x += bb.x; v.y += bb.y;
                }
                if (flags & GF_GELU) {
                    v.x = 0.5f * v.x * (1.0f + erff(v.x * 0.70710678118654752f));
                    v.y = 0.5f * v.y * (1.0f + erff(v.y * 0.70710678118654752f));
                }
                if (flags & GF_ADDC) {
                    float2 o = *(const float2*)&crow[cc];
                    v.x += o.x; v.y += o.y;
                }
                *(float2*)&crow[cc] = v;
            }
        }
    }
}

// ---------------- generic batched GEMM kernel ---------------------------------------
#define GF_CAUSAL 4
#define GF_KLIM   8

template<bool TRANSB>
__global__ void __launch_bounds__(256, 2)
hmma_gemm(const float* __restrict__ A, const float* __restrict__ B,
          float* __restrict__ C, const float* __restrict__ bias,
          int K, int lda, int ldb, int ldc,
          long sAb, long sAh, long sBb, long sBh, long sCb, long sCh,
          long sBiash, int nH, int flags) {
    int bx = blockIdx.x, by = blockIdx.y;
    if ((flags & GF_CAUSAL) && bx > by) return;
    if (flags & GF_KLIM) K = min(K, (by + 1) * 128);

    int z  = blockIdx.z;
    int zb = z / nH, zh = z % nH;
    A += (size_t)zb * sAb + (size_t)zh * sAh;
    B += (size_t)zb * sBb + (size_t)zh * sBh;
    C += (size_t)zb * sCb + (size_t)zh * sCh;
    if (bias) bias += (size_t)zh * sBiash;

    gemm_body<TRANSB>(A, B, C, bias, K, lda, ldb, ldc, bx, by, flags);
}

// ---------------- fused QKV kernel (z = 0..3*H-1, sel = z/H) -------------------------
__global__ void __launch_bounds__(256, 2)
qkv_gemm(const float* __restrict__ A,
         const float* __restrict__ Wq, const float* __restrict__ Wk, const float* __restrict__ Wv,
         const float* __restrict__ bq, const float* __restrict__ bk, const float* __restrict__ bv,
         float* __restrict__ Cq, float* __restrict__ Ck, float* __restrict__ Cv) {
    int z = blockIdx.z;
    int sel = z >> 2;        // H_ == 4
    int zh  = z & 3;
    const float* W = (sel == 0) ? Wq : (sel == 1) ? Wk : Wv;
    const float* bb = (sel == 0) ? bq : (sel == 1) ? bk : bv;
    float* C = (sel == 0) ? Cq : (sel == 1) ? Ck : Cv;
    W  += (size_t)zh * D_ * D_;
    bb += (size_t)zh * D_;
    C  += (size_t)zh * (size_t)M_ * D_;
    gemm_body<false>(A, W, C, bb, D_, D_, D_, D_, blockIdx.x, blockIdx.y, 0);
}

// ---------------- host-side launcher -------------------------------------------------
static void launch_gemm(bool transB, const float* A, const float* B, float* C,
                        const float* bias, int M, int N, int K,
                        int lda, int ldb, int ldc,
                        long sAb, long sAh, long sBb, long sBh,
                        long sCb, long sCh, long sBiash,
                        int nB, int nH, int flags) {
    dim3 grid(N / 128, M / 128, nB * nH);
    if (transB)
        hmma_gemm<true><<<grid, 256, SMEM_REQ>>>(A, B, C, bias, K, lda, ldb, ldc,
                                                 sAb, sAh, sBb, sBh, sCb, sCh, sBiash, nH, flags);
    else
        hmma_gemm<false><<<grid, 256, SMEM_REQ>>>(A, B, C, bias, K, lda, ldb, ldc,
                                                  sAb, sAh, sBb, sBh, sCb, sCh, sBiash, nH, flags);
}

extern "C" void kernel_launch(void* const* d_in, const int* in_sizes, int n_in,
                              void* d_out, int out_size) {
    const int*   x         = (const int*)  d_in[0];
    const float* token_emb = (const float*)d_in[1];
    const float* Wq   = (const float*)d_in[2];
    const float* bq   = (const float*)d_in[3];
    const float* Wk   = (const float*)d_in[4];
    const float* bk   = (const float*)d_in[5];
    const float* Wv   = (const float*)d_in[6];
    const float* bv   = (const float*)d_in[7];
    const float* Wo   = (const float*)d_in[8];
    const float* bo   = (const float*)d_in[9];
    const float* ln1g = (const float*)d_in[10];
    const float* ln1b = (const float*)d_in[11];
    const float* ln2g = (const float*)d_in[12];
    const float* ln2b = (const float*)d_in[13];
    const float* W1   = (const float*)d_in[14];
    const float* b1   = (const float*)d_in[15];
    const float* W2   = (const float*)d_in[16];
    const float* b2   = (const float*)d_in[17];
    const float* flng = (const float*)d_in[18];
    const float* flnb = (const float*)d_in[19];
    const float* Wout = (const float*)d_in[20];
    float* out = (float*)d_out;

    cudaFuncSetAttribute(hmma_gemm<false>, cudaFuncAttributeMaxDynamicSharedMemorySize, SMEM_REQ);
    cudaFuncSetAttribute(hmma_gemm<true>,  cudaFuncAttributeMaxDynamicSharedMemorySize, SMEM_REQ);
    cudaFuncSetAttribute(qkv_gemm,         cudaFuncAttributeMaxDynamicSharedMemorySize, SMEM_REQ);

    float *ph, *pxn, *pq, *pk, *pv, *ps, *py, *pff;
    cudaGetSymbolAddress((void**)&ph,  g_h);
    cudaGetSymbolAddress((void**)&pxn, g_xn);
    cudaGetSymbolAddress((void**)&pq,  g_q);
    cudaGetSymbolAddress((void**)&pk,  g_k);
    cudaGetSymbolAddress((void**)&pv,  g_v);
    cudaGetSymbolAddress((void**)&ps,  g_s);
    cudaGetSymbolAddress((void**)&py,  g_y);
    cudaGetSymbolAddress((void**)&pff, g_ff);

    embed_kernel<<<M_, 256>>>(x, token_emb, ph);

    for (int l = 0; l < L_; l++) {
        layernorm_kernel<<<M_, 256>>>(ph, pxn, ln1g + (size_t)l * D_, ln1b + (size_t)l * D_);

        const long wOff = (long)l * H_ * D_ * D_;
        const long bOff = (long)l * H_ * D_;
        // fused Q/K/V projection: one launch, 12 batch slices
        {
            dim3 grid(D_ / 128, M_ / 128, 3 * H_);
            qkv_gemm<<<grid, 256, SMEM_REQ>>>(pxn,
                Wq + wOff, Wk + wOff, Wv + wOff,
                bq + bOff, bk + bOff, bv + bOff,
                pq, pk, pv);
        }

        // S = Q @ K^T per (b,h): B (K matrix) is [T,D] = [N,K] native layout
        launch_gemm(true, pq, pk, ps, nullptr,
                    T_, T_, D_, D_, D_, T_,
                    (long)T_ * D_, (long)M_ * D_,
                    (long)T_ * D_, (long)M_ * D_,
                    (long)H_ * T_ * T_, (long)T_ * T_,
                    0, B_, H_, GF_CAUSAL);

        attn_softmax_kernel<<<B_ * H_ * T_, 256>>>(ps);

        launch_gemm(false, ps, pv, py, nullptr,
                    T_, D_, T_, T_, D_, H_ * D_,
                    (long)H_ * T_ * T_, (long)T_ * T_,
                    (long)T_ * D_, (long)M_ * D_,
                    (long)T_ * H_ * D_, (long)D_,
                    0, B_, H_, GF_KLIM);

        launch_gemm(false, py, Wo + (long)l * H_ * D_ * D_, ph, bo + (long)l * D_,
                    M_, D_, H_ * D_, H_ * D_, D_, D_,
                    0, 0, 0, 0, 0, 0, 0, 1, 1, GF_ADDC);

        layernorm_kernel<<<M_, 256>>>(ph, pxn, ln2g + (size_t)l * D_, ln2b + (size_t)l * D_);

        launch_gemm(false, pxn, W1 + (long)l * D_ * DFF_, pff, b1 + (long)l * DFF_,
                    M_, DFF_, D_, D_, DFF_, DFF_,
                    0, 0, 0, 0, 0, 0, 0, 1, 1, GF_GELU);

        launch_gemm(false, pff, W2 + (long)l * DFF_ * D_, ph, b2 + (long)l * D_,
                    M_, D_, DFF_, DFF_, D_, D_,
                    0, 0, 0, 0, 0, 0, 0, 1, 1, GF_ADDC);
    }

    layernorm_kernel<<<M_, 256>>>(ph, pxn, flng, flnb);

    launch_gemm(false, pxn, Wout, out, nullptr,
                M_, V_, D_, D_, V_, V_,
                0, 0, 0, 0, 0, 0, 0, 1, 1, 0);

    logsoftmax_kernel<<<M_, 256>>>(out);
}

// round 7
// speedup vs baseline: 4.3357x; 1.0436x over previous
#include <cuda_runtime.h>
#include <cstdint>
#include <math.h>

#define L_   4
#define H_   4
#define B_   2
#define T_   1024
#define D_   1024
#define DFF_ 4096
#define V_   32000
#define M_   (B_*T_)   // 2048 tokens

// ---------------- scratch (static device globals; no allocs allowed) ----------
__device__ float g_h [M_*D_];
__device__ float g_xn[M_*D_];
__device__ float g_q [H_*M_*D_];
__device__ float g_k [H_*M_*D_];
__device__ float g_v [H_*M_*D_];
__device__ float g_s [B_*H_*T_*T_];
__device__ float g_y [M_*H_*D_];
__device__ float g_ff[M_*DFF_];

// ---------------- helpers -------------------------------------------------------
__device__ __forceinline__ uint32_t smem_u32(const void* p) {
    uint32_t a;
    asm("{ .reg .u64 t; cvta.to.shared.u64 t, %1; cvt.u32.u64 %0, t; }" : "=r"(a) : "l"(p));
    return a;
}
__device__ __forceinline__ void cpa16(uint32_t dst, const void* src) {
    asm volatile("cp.async.cg.shared.global [%0], [%1], 16;" :: "r"(dst), "l"(src) : "memory");
}
#define CP_COMMIT() asm volatile("cp.async.commit_group;" ::: "memory")
#define CP_WAIT(n)  asm volatile("cp.async.wait_group %0;" :: "n"(n) : "memory")

__device__ __forceinline__ void mma_tf32(float* c, const uint32_t* a, const uint32_t* b) {
    asm volatile("mma.sync.aligned.m16n8k8.row.col.f32.tf32.tf32.f32 "
        "{%0,%1,%2,%3}, {%4,%5,%6,%7}, {%8,%9}, {%0,%1,%2,%3};"
        : "+f"(c[0]), "+f"(c[1]), "+f"(c[2]), "+f"(c[3])
        : "r"(a[0]), "r"(a[1]), "r"(a[2]), "r"(a[3]), "r"(b[0]), "r"(b[1]));
}
__device__ __forceinline__ void ldsm4(uint32_t* r, uint32_t addr) {
    asm volatile("ldmatrix.sync.aligned.m8n8.x4.shared.b16 {%0,%1,%2,%3}, [%4];"
        : "=r"(r[0]), "=r"(r[1]), "=r"(r[2]), "=r"(r[3]) : "r"(addr));
}

// ---------------- fast exp on the FMA pipe --------------------------------------
__device__ __forceinline__ float fexp(float x) {
    x = fmaxf(x, -80.f);
    float z = x * 1.4426950408889634f;
    float y = z + 12582912.0f;
    float n = y - 12582912.0f;
    float t = fmaf(n, -0.6931471805599453f, x);
    float p =             0.008333333f;
    p = fmaf(p, t, 0.041666668f);
    p = fmaf(p, t, 0.16666667f);
    p = fmaf(p, t, 0.5f);
    p = fmaf(p, t, 1.0f);
    p = fmaf(p, t, 1.0f);
    int e = __float_as_int(y) - 0x4B400000;
    return p * __int_as_float((127 + e) << 23);
}

// ---------------- block reductions ----------------------------------------------
__device__ __forceinline__ float blockReduceSum(float v) {
    __shared__ float sh[9];
    int lane = threadIdx.x & 31, w = threadIdx.x >> 5;
    #pragma unroll
    for (int o = 16; o; o >>= 1) v += __shfl_xor_sync(0xffffffffu, v, o);
    if (lane == 0) sh[w] = v;
    __syncthreads();
    if (threadIdx.x == 0) {
        float s = 0.f;
        #pragma unroll
        for (int i = 0; i < 8; i++) s += sh[i];
        sh[8] = s;
    }
    __syncthreads();
    float r = sh[8];
    __syncthreads();
    return r;
}
__device__ __forceinline__ float blockReduceMax(float v) {
    __shared__ float sh[9];
    int lane = threadIdx.x & 31, w = threadIdx.x >> 5;
    #pragma unroll
    for (int o = 16; o; o >>= 1) v = fmaxf(v, __shfl_xor_sync(0xffffffffu, v, o));
    if (lane == 0) sh[w] = v;
    __syncthreads();
    if (threadIdx.x == 0) {
        float s = sh[0];
        #pragma unroll
        for (int i = 1; i < 8; i++) s = fmaxf(s, sh[i]);
        sh[8] = s;
    }
    __syncthreads();
    float r = sh[8];
    __syncthreads();
    return r;
}

// ---------------- embedding ------------------------------------------------------
__global__ void embed_kernel(const int* __restrict__ x,
                             const float* __restrict__ emb,
                             float* __restrict__ h) {
    int m = blockIdx.x;
    int t = m % T_;
    int tok = x[m];
    const float* erow = emb + (size_t)tok * D_;
    float* hrow = h + (size_t)m * D_;
    for (int d = threadIdx.x; d < D_; d += blockDim.x) {
        int i = d >> 1;
        float denom = powf(10000.f, (2.f * (float)i) / (float)D_);
        float ang = (float)t / denom;
        float pe = (d & 1) ? cosf(ang) : sinf(ang);
        hrow[d] = erow[d] + pe;
    }
}

// ---------------- layernorm -------------------------------------------------------
__global__ void layernorm_kernel(const float* __restrict__ in,
                                 float* __restrict__ out,
                                 const float* __restrict__ g,
                                 const float* __restrict__ b) {
    int m = blockIdx.x;
    int tid = threadIdx.x;
    const float4* x4 = (const float4*)(in + (size_t)m * D_);
    float4 v = x4[tid];
    float s = v.x + v.y + v.z + v.w;
    s = blockReduceSum(s);
    float mean = s * (1.0f / D_);
    float dx = v.x - mean, dy = v.y - mean, dz = v.z - mean, dw = v.w - mean;
    float q = dx*dx + dy*dy + dz*dz + dw*dw;
    q = blockReduceSum(q);
    float inv = rsqrtf(q * (1.0f / D_) + 1e-5f);
    float4 gg = ((const float4*)g)[tid];
    float4 bb = ((const float4*)b)[tid];
    float4 o;
    o.x = dx * inv * gg.x + bb.x;
    o.y = dy * inv * gg.y + bb.y;
    o.z = dz * inv * gg.z + bb.z;
    o.w = dw * inv * gg.w + bb.w;
    ((float4*)(out + (size_t)m * D_))[tid] = o;
}

// ---------------- causal softmax ---------------------------------------------------
__global__ void attn_softmax_kernel(float* __restrict__ S) {
    int r = blockIdx.x;            // 0 .. B*H*T-1
    int t = r % T_;
    int z = r / T_;
    float* row = S + (size_t)z * T_ * T_ + (size_t)t * T_;
    const float scale = 0.03125f;  // 1/sqrt(1024)
    int tid = threadIdx.x;
    float v[4];
    #pragma unroll
    for (int i = 0; i < 4; i++) {
        int s = tid + 256 * i;
        v[i] = (s <= t) ? row[s] * scale : -INFINITY;
    }
    float lmax = fmaxf(fmaxf(v[0], v[1]), fmaxf(v[2], v[3]));
    float mx = blockReduceMax(lmax);
    float e[4]; float lsum = 0.f;
    #pragma unroll
    for (int i = 0; i < 4; i++) {
        int s = tid + 256 * i;
        e[i] = (s <= t) ? fexp(v[i] - mx) : 0.f;
        lsum += e[i];
    }
    float sum = blockReduceSum(lsum);
    float invs = 1.0f / sum;
    #pragma unroll
    for (int i = 0; i < 4; i++) {
        int s = tid + 256 * i;
        row[s] = e[i] * invs;
    }
}

// ---------------- final log-softmax: row cached in SMEM (1 read + 1 write) ---------
__global__ void logsoftmax_kernel(float* __restrict__ out) {
    extern __shared__ float sv[];
    float* row = out + (size_t)blockIdx.x * V_;
    int tid = threadIdx.x;
    float lmax = -INFINITY;
    for (int i = tid * 4; i < V_; i += 1024) {
        float4 v = *(const float4*)&row[i];
        *(float4*)&sv[i] = v;
        lmax = fmaxf(lmax, fmaxf(fmaxf(v.x, v.y), fmaxf(v.z, v.w)));
    }
    float mx = blockReduceMax(lmax);
    float lsum = 0.f;
    for (int i = tid; i < V_; i += 256) lsum += fexp(sv[i] - mx);
    float sum = blockReduceSum(lsum);
    float lse = logf(sum) + mx;
    for (int i = tid * 4; i < V_; i += 1024) {
        float4 v = *(const float4*)&sv[i];
        v.x -= lse; v.y -= lse; v.z -= lse; v.w -= lse;
        *(float4*)&row[i] = v;
    }
}

// ---------------- HMMA tf32 GEMM body: 3-stage cp.async, ldmatrix fragments --------
// CTA 128x128, K-tile 32, 8 warps (2m x 4n), warp 64x32 via m16n8k8 tf32 HMMA.
// A (and B when TRANSB): SMEM [row][32] fp32 bits, XOR swizzle c ^= (row&7)<<2.
// B when !TRANSB: natural [k][136] padded rows.
// fp32 operands fed to tf32 MMA raw (bits[31:13] truncation).
#define GF_ADDC   1
#define GF_GELU   2

#define A_BYTES   16384                 // 128 x 32 x 4
#define BN_BYTES  17408                 // 32 x 136 x 4  (covers TRANSB's 16384 too)
#define STAGE     (A_BYTES + BN_BYTES)  // 33792
#define NSTAGE    3
#define SMEM_REQ  (NSTAGE * STAGE)      // 101376

template<bool TRANSB>
__device__ __forceinline__ void gemm_body(
        const float* __restrict__ A, const float* __restrict__ B,
        float* __restrict__ C, const float* __restrict__ bias,
        int K, int lda, int ldb, int ldc, int bx, int by, int flags) {
    extern __shared__ char sm[];
    const uint32_t smBase = smem_u32(sm);

    const int tid = threadIdx.x;
    const int wid = tid >> 5, lane = tid & 31;
    const int lr = lane >> 2, lc = lane & 3;
    const int wm = wid & 1, wn = wid >> 1;      // warp tile: rows wm*64, cols wn*32
    const int sxor = (lane & 7) << 2;

    // ldmatrix lane->address mapping
    // A x4: m0=(r,c) m1=(r+8,c) m2=(r,c+4) m3=(r+8,c+4)
    const int aRowL = ((lane >> 3) & 1) * 8 + (lane & 7);
    const int aCol4 = (lane >> 4) << 2;               // 0 or 4
    const uint32_t aLaneOff = (uint32_t)((wm * 64 + aRowL) * 128);
    // B x4 (TRANSB): m0=(n,c) m1=(n,c+4) m2=(n+8,c) m3=(n+8,c+4)
    const int bRowL = ((lane >> 4) & 1) * 8 + (lane & 7);
    const int bCol4 = ((lane >> 3) & 1) << 2;
    const uint32_t bLaneOff = (uint32_t)((wn * 32 + bRowL) * 128);

    // A staging: thread -> row tid>>1, 16B chunks (tid&1)*4 + j (j=0..3), swizzled
    const int sr  = tid >> 1;
    const int sc4 = (tid & 1) << 2;
    const float* Arow = A + (size_t)(by * 128 + sr) * lda;
    const float* Brow = TRANSB ? (B + (size_t)(bx * 128 + sr) * ldb) : nullptr;
    const int bk  = tid >> 3;
    const int bc  = tid & 7;
    const float* Bk = TRANSB ? nullptr : (B + (size_t)bk * ldb + (size_t)bx * 128);

    auto issue = [&](int kt, int s) {
        uint32_t dA = smBase + s * STAGE;
        uint32_t dB = dA + A_BYTES;
        const float* a = Arow + kt * 32;
        #pragma unroll
        for (int j = 0; j < 4; j++) {
            int c0 = (sc4 + j) << 2;
            int scol = c0 ^ ((sr & 7) << 2);
            cpa16(dA + (uint32_t)(sr * 128 + scol * 4), a + c0);
        }
        if (TRANSB) {
            const float* b = Brow + kt * 32;
            #pragma unroll
            for (int j = 0; j < 4; j++) {
                int c0 = (sc4 + j) << 2;
                int scol = c0 ^ ((sr & 7) << 2);
                cpa16(dB + (uint32_t)(sr * 128 + scol * 4), b + c0);
            }
        } else {
            const float* b = Bk + (size_t)kt * 32 * ldb;
            #pragma unroll
            for (int j = 0; j < 4; j++) {
                int ch = bc + 8 * j;
                cpa16(dB + (uint32_t)(bk * 544 + ch * 16), b + ch * 4);
            }
        }
        CP_COMMIT();
    };

    float acc[4][4][4];
    #pragma unroll
    for (int i = 0; i < 4; i++)
        #pragma unroll
        for (int j = 0; j < 4; j++)
            #pragma unroll
            for (int q = 0; q < 4; q++) acc[i][j][q] = 0.f;

    auto compute = [&](int s) {
        const uint32_t AbA = smBase + s * STAGE;
        const uint32_t BbA = AbA + A_BYTES;
        const uint32_t* Bb = (const uint32_t*)(sm + s * STAGE + A_BYTES);
        #pragma unroll
        for (int ks = 0; ks < 4; ks++) {
            uint32_t a[4][4], b[4][2];
            uint32_t aC = (uint32_t)(((ks * 8 + aCol4) ^ sxor) << 2);
            #pragma unroll
            for (int mt = 0; mt < 4; mt++)
                ldsm4(a[mt], AbA + aLaneOff + mt * 2048 + aC);
            if (TRANSB) {
                uint32_t bC = (uint32_t)(((ks * 8 + bCol4) ^ sxor) << 2);
                ldsm4(&b[0][0], BbA + bLaneOff + bC);
                ldsm4(&b[2][0], BbA + bLaneOff + 2048 + bC);
            } else {
                int n0 = wn * 32 + lr;
                #pragma unroll
                for (int nt = 0; nt < 4; nt++) {
                    b[nt][0] = Bb[(ks * 8 + lc) * 136 + n0 + nt * 8];
                    b[nt][1] = Bb[(ks * 8 + lc + 4) * 136 + n0 + nt * 8];
                }
            }
            #pragma unroll
            for (int mt = 0; mt < 4; mt++)
                #pragma unroll
                for (int nt = 0; nt < 4; nt++)
                    mma_tf32(acc[mt][nt], a[mt], b[nt]);
        }
    };

    int ktiles = K >> 5;               // always >= 4 here
    issue(0, 0);
    issue(1, 1);

    for (int kt = 0; kt < ktiles; kt++) {
        int buf = kt % NSTAGE;
        if (kt + 1 < ktiles) { CP_WAIT(1); } else { CP_WAIT(0); }
        __syncthreads();
        compute(buf);
        if (kt + 2 < ktiles) issue(kt + 2, (kt + 2) % NSTAGE);
    }

    // epilogue
    #pragma unroll
    for (int mt = 0; mt < 4; mt++) {
        int r0 = by * 128 + wm * 64 + mt * 16 + lr;
        #pragma unroll
        for (int half = 0; half < 2; half++) {
            int r = r0 + 8 * half;
            float* crow = C + (size_t)r * ldc;
            #pragma unroll
            for (int nt = 0; nt < 4; nt++) {
                int cc = bx * 128 + wn * 32 + nt * 8 + 2 * lc;
                float2 v = make_float2(acc[mt][nt][2 * half], acc[mt][nt][2 * half + 1]);
                if (bias) {
                    float2 bb = *(const float2*)&bias[cc];
                    v.x += bb.x; v.y += bb.y;
                }
                if (flags & GF_GELU) {
                    v.x = 0.5f * v.x * (1.0f + erff(v.x * 0.70710678118654752f));
                    v.y = 0.5f * v.y * (1.0f + erff(v.y * 0.70710678118654752f));
                }
                if (flags & GF_ADDC) {
                    float2 o = *(const float2*)&crow[cc];
                    v.x += o.x; v.y += o.y;
                }
                *(float2*)&crow[cc] = v;
            }
        }
    }
}

// ---------------- generic batched GEMM kernel ---------------------------------------
#define GF_CAUSAL 4
#define GF_KLIM   8

template<bool TRANSB>
__global__ void __launch_bounds__(256, 2)
hmma_gemm(const float* __restrict__ A, const float* __restrict__ B,
          float* __restrict__ C, const float* __restrict__ bias,
          int K, int lda, int ldb, int ldc,
          long sAb, long sAh, long sBb, long sBh, long sCb, long sCh,
          long sBiash, int nH, int flags) {
    int bx = blockIdx.x, by = blockIdx.y;
    if ((flags & GF_CAUSAL) && bx > by) return;
    if (flags & GF_KLIM) K = min(K, (by + 1) * 128);

    int z  = blockIdx.z;
    int zb = z / nH, zh = z % nH;
    A += (size_t)zb * sAb + (size_t)zh * sAh;
    B += (size_t)zb * sBb + (size_t)zh * sBh;
    C += (size_t)zb * sCb + (size_t)zh * sCh;
    if (bias) bias += (size_t)zh * sBiash;

    gemm_body<TRANSB>(A, B, C, bias, K, lda, ldb, ldc, bx, by, flags);
}

// ---------------- fused QKV kernel (z = 0..3*H-1, sel = z/H) -------------------------
__global__ void __launch_bounds__(256, 2)
qkv_gemm(const float* __restrict__ A,
         const float* __restrict__ Wq, const float* __restrict__ Wk, const float* __restrict__ Wv,
         const float* __restrict__ bq, const float* __restrict__ bk, const float* __restrict__ bv,
         float* __restrict__ Cq, float* __restrict__ Ck, float* __restrict__ Cv) {
    int z = blockIdx.z;
    int sel = z >> 2;        // H_ == 4
    int zh  = z & 3;
    const float* W = (sel == 0) ? Wq : (sel == 1) ? Wk : Wv;
    const float* bb = (sel == 0) ? bq : (sel == 1) ? bk : bv;
    float* C = (sel == 0) ? Cq : (sel == 1) ? Ck : Cv;
    W  += (size_t)zh * D_ * D_;
    bb += (size_t)zh * D_;
    C  += (size_t)zh * (size_t)M_ * D_;
    gemm_body<false>(A, W, C, bb, D_, D_, D_, D_, blockIdx.x, blockIdx.y, 0);
}

// ---------------- host-side launcher -------------------------------------------------
static void launch_gemm(bool transB, const float* A, const float* B, float* C,
                        const float* bias, int M, int N, int K,
                        int lda, int ldb, int ldc,
                        long sAb, long sAh, long sBb, long sBh,
                        long sCb, long sCh, long sBiash,
                        int nB, int nH, int flags) {
    dim3 grid(N / 128, M / 128, nB * nH);
    if (transB)
        hmma_gemm<true><<<grid, 256, SMEM_REQ>>>(A, B, C, bias, K, lda, ldb, ldc,
                                                 sAb, sAh, sBb, sBh, sCb, sCh, sBiash, nH, flags);
    else
        hmma_gemm<false><<<grid, 256, SMEM_REQ>>>(A, B, C, bias, K, lda, ldb, ldc,
                                                  sAb, sAh, sBb, sBh, sCb, sCh, sBiash, nH, flags);
}

extern "C" void kernel_launch(void* const* d_in, const int* in_sizes, int n_in,
                              void* d_out, int out_size) {
    const int*   x         = (const int*)  d_in[0];
    const float* token_emb = (const float*)d_in[1];
    const float* Wq   = (const float*)d_in[2];
    const float* bq   = (const float*)d_in[3];
    const float* Wk   = (const float*)d_in[4];
    const float* bk   = (const float*)d_in[5];
    const float* Wv   = (const float*)d_in[6];
    const float* bv   = (const float*)d_in[7];
    const float* Wo   = (const float*)d_in[8];
    const float* bo   = (const float*)d_in[9];
    const float* ln1g = (const float*)d_in[10];
    const float* ln1b = (const float*)d_in[11];
    const float* ln2g = (const float*)d_in[12];
    const float* ln2b = (const float*)d_in[13];
    const float* W1   = (const float*)d_in[14];
    const float* b1   = (const float*)d_in[15];
    const float* W2   = (const float*)d_in[16];
    const float* b2   = (const float*)d_in[17];
    const float* flng = (const float*)d_in[18];
    const float* flnb = (const float*)d_in[19];
    const float* Wout = (const float*)d_in[20];
    float* out = (float*)d_out;

    cudaFuncSetAttribute(hmma_gemm<false>, cudaFuncAttributeMaxDynamicSharedMemorySize, SMEM_REQ);
    cudaFuncSetAttribute(hmma_gemm<true>,  cudaFuncAttributeMaxDynamicSharedMemorySize, SMEM_REQ);
    cudaFuncSetAttribute(qkv_gemm,         cudaFuncAttributeMaxDynamicSharedMemorySize, SMEM_REQ);
    cudaFuncSetAttribute(logsoftmax_kernel, cudaFuncAttributeMaxDynamicSharedMemorySize, V_ * 4);

    float *ph, *pxn, *pq, *pk, *pv, *ps, *py, *pff;
    cudaGetSymbolAddress((void**)&ph,  g_h);
    cudaGetSymbolAddress((void**)&pxn, g_xn);
    cudaGetSymbolAddress((void**)&pq,  g_q);
    cudaGetSymbolAddress((void**)&pk,  g_k);
    cudaGetSymbolAddress((void**)&pv,  g_v);
    cudaGetSymbolAddress((void**)&ps,  g_s);
    cudaGetSymbolAddress((void**)&py,  g_y);
    cudaGetSymbolAddress((void**)&pff, g_ff);

    embed_kernel<<<M_, 256>>>(x, token_emb, ph);

    for (int l = 0; l < L_; l++) {
        layernorm_kernel<<<M_, 256>>>(ph, pxn, ln1g + (size_t)l * D_, ln1b + (size_t)l * D_);

        const long wOff = (long)l * H_ * D_ * D_;
        const long bOff = (long)l * H_ * D_;
        // fused Q/K/V projection: one launch, 12 batch slices
        {
            dim3 grid(D_ / 128, M_ / 128, 3 * H_);
            qkv_gemm<<<grid, 256, SMEM_REQ>>>(pxn,
                Wq + wOff, Wk + wOff, Wv + wOff,
                bq + bOff, bk + bOff, bv + bOff,
                pq, pk, pv);
        }

        // S = Q @ K^T per (b,h): B (K matrix) is [T,D] = [N,K] native layout
        launch_gemm(true, pq, pk, ps, nullptr,
                    T_, T_, D_, D_, D_, T_,
                    (long)T_ * D_, (long)M_ * D_,
                    (long)T_ * D_, (long)M_ * D_,
                    (long)H_ * T_ * T_, (long)T_ * T_,
                    0, B_, H_, GF_CAUSAL);

        attn_softmax_kernel<<<B_ * H_ * T_, 256>>>(ps);

        launch_gemm(false, ps, pv, py, nullptr,
                    T_, D_, T_, T_, D_, H_ * D_,
                    (long)H_ * T_ * T_, (long)T_ * T_,
                    (long)T_ * D_, (long)M_ * D_,
                    (long)T_ * H_ * D_, (long)D_,
                    0, B_, H_, GF_KLIM);

        launch_gemm(false, py, Wo + (long)l * H_ * D_ * D_, ph, bo + (long)l * D_,
                    M_, D_, H_ * D_, H_ * D_, D_, D_,
                    0, 0, 0, 0, 0, 0, 0, 1, 1, GF_ADDC);

        layernorm_kernel<<<M_, 256>>>(ph, pxn, ln2g + (size_t)l * D_, ln2b + (size_t)l * D_);

        launch_gemm(false, pxn, W1 + (long)l * D_ * DFF_, pff, b1 + (long)l * DFF_,
                    M_, DFF_, D_, D_, DFF_, DFF_,
                    0, 0, 0, 0, 0, 0, 0, 1, 1, GF_GELU);

        launch_gemm(false, pff, W2 + (long)l * DFF_ * D_, ph, b2 + (long)l * D_,
                    M_, D_, DFF_, DFF_, D_, D_,
                    0, 0, 0, 0, 0, 0, 0, 1, 1, GF_ADDC);
    }

    layernorm_kernel<<<M_, 256>>>(ph, pxn, flng, flnb);

    launch_gemm(false, pxn, Wout, out, nullptr,
                M_, V_, D_, D_, V_, V_,
                0, 0, 0, 0, 0, 0, 0, 1, 1, 0);

    logsoftmax_kernel<<<M_, 256, V_ * 4>>>(out);
}

// round 8
// speedup vs baseline: 6.7253x; 1.5511x over previous
#include <cuda_runtime.h>
#include <cuda_fp16.h>
#include <cstdint>
#include <math.h>

#define L_   4
#define H_   4
#define B_   2
#define T_   1024
#define D_   1024
#define DFF_ 4096
#define V_   32000
#define M_   (B_*T_)   // 2048 tokens

// ---------------- scratch (static device globals; no allocs allowed) ----------
__device__ float  g_h [M_*D_];          // residual (fp32)
__device__ float  g_s [B_*H_*T_*T_];    // attention scores (fp32)
__device__ __half g_xn[M_*D_];          // LN output (fp16)
__device__ __half g_q [H_*M_*D_];
__device__ __half g_k [H_*M_*D_];
__device__ __half g_v [H_*M_*D_];
__device__ __half g_a [B_*H_*T_*T_];    // softmax probs (fp16)
__device__ __half g_y [M_*H_*D_];
__device__ __half g_ff[M_*DFF_];
// fp16 weight mirrors
__device__ __half g_wq[L_*H_*D_*D_];
__device__ __half g_wk[L_*H_*D_*D_];
__device__ __half g_wv[L_*H_*D_*D_];
__device__ __half g_wo[L_*H_*D_*D_];
__device__ __half g_w1[L_*D_*DFF_];
__device__ __half g_w2[L_*DFF_*D_];
__device__ __half g_wout[D_*V_];

// ---------------- helpers -------------------------------------------------------
__device__ __forceinline__ uint32_t smem_u32(const void* p) {
    uint32_t a;
    asm("{ .reg .u64 t; cvta.to.shared.u64 t, %1; cvt.u32.u64 %0, t; }" : "=r"(a) : "l"(p));
    return a;
}
__device__ __forceinline__ void cpa16(uint32_t dst, const void* src) {
    asm volatile("cp.async.cg.shared.global [%0], [%1], 16;" :: "r"(dst), "l"(src) : "memory");
}
#define CP_COMMIT() asm volatile("cp.async.commit_group;" ::: "memory")
#define CP_WAIT(n)  asm volatile("cp.async.wait_group %0;" :: "n"(n) : "memory")

__device__ __forceinline__ void mma_f16(float* c, const uint32_t* a, const uint32_t* b) {
    asm volatile("mma.sync.aligned.m16n8k16.row.col.f32.f16.f16.f32 "
        "{%0,%1,%2,%3}, {%4,%5,%6,%7}, {%8,%9}, {%0,%1,%2,%3};"
        : "+f"(c[0]), "+f"(c[1]), "+f"(c[2]), "+f"(c[3])
        : "r"(a[0]), "r"(a[1]), "r"(a[2]), "r"(a[3]), "r"(b[0]), "r"(b[1]));
}
__device__ __forceinline__ void ldsm4(uint32_t* r, uint32_t addr) {
    asm volatile("ldmatrix.sync.aligned.m8n8.x4.shared.b16 {%0,%1,%2,%3}, [%4];"
        : "=r"(r[0]), "=r"(r[1]), "=r"(r[2]), "=r"(r[3]) : "r"(addr));
}
__device__ __forceinline__ void ldsm4t(uint32_t* r, uint32_t addr) {
    asm volatile("ldmatrix.sync.aligned.m8n8.x4.trans.shared.b16 {%0,%1,%2,%3}, [%4];"
        : "=r"(r[0]), "=r"(r[1]), "=r"(r[2]), "=r"(r[3]) : "r"(addr));
}

// ---------------- fast exp on the FMA pipe --------------------------------------
__device__ __forceinline__ float fexp(float x) {
    x = fmaxf(x, -80.f);
    float z = x * 1.4426950408889634f;
    float y = z + 12582912.0f;
    float n = y - 12582912.0f;
    float t = fmaf(n, -0.6931471805599453f, x);
    float p =             0.008333333f;
    p = fmaf(p, t, 0.041666668f);
    p = fmaf(p, t, 0.16666667f);
    p = fmaf(p, t, 0.5f);
    p = fmaf(p, t, 1.0f);
    p = fmaf(p, t, 1.0f);
    int e = __float_as_int(y) - 0x4B400000;
    return p * __int_as_float((127 + e) << 23);
}

// ---------------- block reductions ----------------------------------------------
__device__ __forceinline__ float blockReduceSum(float v) {
    __shared__ float sh[9];
    int lane = threadIdx.x & 31, w = threadIdx.x >> 5;
    #pragma unroll
    for (int o = 16; o; o >>= 1) v += __shfl_xor_sync(0xffffffffu, v, o);
    if (lane == 0) sh[w] = v;
    __syncthreads();
    if (threadIdx.x == 0) {
        float s = 0.f;
        #pragma unroll
        for (int i = 0; i < 8; i++) s += sh[i];
        sh[8] = s;
    }
    __syncthreads();
    float r = sh[8];
    __syncthreads();
    return r;
}
__device__ __forceinline__ float blockReduceMax(float v) {
    __shared__ float sh[9];
    int lane = threadIdx.x & 31, w = threadIdx.x >> 5;
    #pragma unroll
    for (int o = 16; o; o >>= 1) v = fmaxf(v, __shfl_xor_sync(0xffffffffu, v, o));
    if (lane == 0) sh[w] = v;
    __syncthreads();
    if (threadIdx.x == 0) {
        float s = sh[0];
        #pragma unroll
        for (int i = 1; i < 8; i++) s = fmaxf(s, sh[i]);
        sh[8] = s;
    }
    __syncthreads();
    float r = sh[8];
    __syncthreads();
    return r;
}

// ---------------- fp32 -> fp16 convert ------------------------------------------
__global__ void f2h_kernel(const float* __restrict__ s, __half* __restrict__ d, int n) {
    int i = (blockIdx.x * blockDim.x + threadIdx.x) * 8;
    if (i >= n) return;
    float4 v0 = *(const float4*)(s + i);
    float4 v1 = *(const float4*)(s + i + 4);
    __half2 h0 = __floats2half2_rn(v0.x, v0.y);
    __half2 h1 = __floats2half2_rn(v0.z, v0.w);
    __half2 h2 = __floats2half2_rn(v1.x, v1.y);
    __half2 h3 = __floats2half2_rn(v1.z, v1.w);
    uint4 u;
    u.x = *(uint32_t*)&h0; u.y = *(uint32_t*)&h1;
    u.z = *(uint32_t*)&h2; u.w = *(uint32_t*)&h3;
    *(uint4*)(d + i) = u;
}

// ---------------- embedding ------------------------------------------------------
__global__ void embed_kernel(const int* __restrict__ x,
                             const float* __restrict__ emb,
                             float* __restrict__ h) {
    int m = blockIdx.x;
    int t = m % T_;
    int tok = x[m];
    const float* erow = emb + (size_t)tok * D_;
    float* hrow = h + (size_t)m * D_;
    for (int d = threadIdx.x; d < D_; d += blockDim.x) {
        int i = d >> 1;
        float denom = powf(10000.f, (2.f * (float)i) / (float)D_);
        float ang = (float)t / denom;
        float pe = (d & 1) ? cosf(ang) : sinf(ang);
        hrow[d] = erow[d] + pe;
    }
}

// ---------------- layernorm (fp32 in, fp16 out) ----------------------------------
__global__ void layernorm_kernel(const float* __restrict__ in,
                                 __half* __restrict__ out,
                                 const float* __restrict__ g,
                                 const float* __restrict__ b) {
    int m = blockIdx.x;
    int tid = threadIdx.x;
    const float4* x4 = (const float4*)(in + (size_t)m * D_);
    float4 v = x4[tid];
    float s = v.x + v.y + v.z + v.w;
    s = blockReduceSum(s);
    float mean = s * (1.0f / D_);
    float dx = v.x - mean, dy = v.y - mean, dz = v.z - mean, dw = v.w - mean;
    float q = dx*dx + dy*dy + dz*dz + dw*dw;
    q = blockReduceSum(q);
    float inv = rsqrtf(q * (1.0f / D_) + 1e-5f);
    float4 gg = ((const float4*)g)[tid];
    float4 bb = ((const float4*)b)[tid];
    __half2 h0 = __floats2half2_rn(dx * inv * gg.x + bb.x, dy * inv * gg.y + bb.y);
    __half2 h1 = __floats2half2_rn(dz * inv * gg.z + bb.z, dw * inv * gg.w + bb.w);
    uint2 u; u.x = *(uint32_t*)&h0; u.y = *(uint32_t*)&h1;
    *(uint2*)(out + (size_t)m * D_ + tid * 4) = u;
}

// ---------------- causal softmax (fp32 scores in, fp16 probs out) ----------------
__global__ void attn_softmax_kernel(const float* __restrict__ S, __half* __restrict__ A) {
    int r = blockIdx.x;            // 0 .. B*H*T-1
    int t = r % T_;
    int z = r / T_;
    const float* row = S + (size_t)z * T_ * T_ + (size_t)t * T_;
    __half* arow = A + (size_t)z * T_ * T_ + (size_t)t * T_;
    const float scale = 0.03125f;  // 1/sqrt(1024)
    int tid = threadIdx.x;
    float v[4];
    #pragma unroll
    for (int i = 0; i < 4; i++) {
        int s = tid + 256 * i;
        v[i] = (s <= t) ? row[s] * scale : -INFINITY;
    }
    float lmax = fmaxf(fmaxf(v[0], v[1]), fmaxf(v[2], v[3]));
    float mx = blockReduceMax(lmax);
    float e[4]; float lsum = 0.f;
    #pragma unroll
    for (int i = 0; i < 4; i++) {
        int s = tid + 256 * i;
        e[i] = (s <= t) ? fexp(v[i] - mx) : 0.f;
        lsum += e[i];
    }
    float sum = blockReduceSum(lsum);
    float invs = 1.0f / sum;
    #pragma unroll
    for (int i = 0; i < 4; i++) {
        int s = tid + 256 * i;
        arow[s] = __float2half(e[i] * invs);
    }
}

// ---------------- final log-softmax: row cached in SMEM --------------------------
__global__ void logsoftmax_kernel(float* __restrict__ out) {
    extern __shared__ float sv[];
    float* row = out + (size_t)blockIdx.x * V_;
    int tid = threadIdx.x;
    float lmax = -INFINITY;
    for (int i = tid * 4; i < V_; i += 1024) {
        float4 v = *(const float4*)&row[i];
        *(float4*)&sv[i] = v;
        lmax = fmaxf(lmax, fmaxf(fmaxf(v.x, v.y), fmaxf(v.z, v.w)));
    }
    float mx = blockReduceMax(lmax);
    float lsum = 0.f;
    for (int i = tid; i < V_; i += 256) lsum += fexp(sv[i] - mx);
    float sum = blockReduceSum(lsum);
    float lse = logf(sum) + mx;
    for (int i = tid * 4; i < V_; i += 1024) {
        float4 v = *(const float4*)&sv[i];
        v.x -= lse; v.y -= lse; v.z -= lse; v.w -= lse;
        *(float4*)&row[i] = v;
    }
}

// ---------------- fp16 HMMA GEMM body: m16n8k16, 3-stage cp.async ----------------
// CTA 128x128, K-tile 64 halves (128B rows), 8 warps (2m x 4n), warp 64x32.
// A (and B when TRANSB): [row][64 halves], 16B-chunk XOR swizzle ch ^= (row&7).
// B !TRANSB: [k][128 halves] (256B rows, 16 chunks), ch ^= (k&7); ldmatrix.trans.
#define GF_ADDC   1
#define GF_GELU   2
#define GF_CAUSAL 4
#define GF_KLIM   8
#define GF_HALF   16

#define A_BYTES   16384                 // 128 x 128B
#define B_BYTES   16384                 // both layouts
#define STAGE     (A_BYTES + B_BYTES)   // 32768
#define NSTAGE    3
#define SMEM_REQ  (NSTAGE * STAGE)      // 98304

template<bool TRANSB>
__device__ __forceinline__ void gemm_body(
        const __half* __restrict__ A, const __half* __restrict__ B,
        void* __restrict__ Cv, const float* __restrict__ bias,
        int K, int lda, int ldb, int ldc, int bx, int by, int flags) {
    extern __shared__ char sm[];
    const uint32_t smBase = smem_u32(sm);

    const int tid = threadIdx.x;
    const int wid = tid >> 5, lane = tid & 31;
    const int lr = lane >> 2, lc = lane & 3;
    const int wm = wid & 1, wn = wid >> 1;      // warp tile: rows wm*64, cols wn*32
    const int lxor = lane & 7;                  // XOR term (row&7 == lane&7 everywhere)

    // ldmatrix lane maps
    const int aRowL = ((lane >> 3) & 1) * 8 + (lane & 7);
    const int aSel  = (lane >> 4) & 1;                    // +8 k  (chunk +1)
    const uint32_t aBase = (uint32_t)((wm * 64 + aRowL) * 128);
    // B TRANSB (n-major rows)
    const int bRowL = ((lane >> 4) & 1) * 8 + (lane & 7);
    const int bSel  = (lane >> 3) & 1;
    const uint32_t bBase = (uint32_t)((wn * 32 + bRowL) * 128);
    // B !TRANSB (k-major rows, ldmatrix.trans)
    const int tKL   = ((lane >> 3) & 1) * 8 + (lane & 7); // k within 16-step
    const int tNSel = (lane >> 4) & 1;                    // +8 n (chunk +1)
    const int tNBase = wn * 4 + tNSel;                    // n-chunk base

    // staging maps
    const int sr  = tid >> 1;                   // A/B-trans row
    const int sc4 = (tid & 1) << 2;             // chunk base (0 or 4)
    const __half* Arow = A + (size_t)(by * 128 + sr) * lda;
    const __half* Brow = TRANSB ? (B + (size_t)(bx * 128 + sr) * ldb) : nullptr;
    const int bk  = tid >> 2;                   // !TRANSB: k row (0..63)
    const int bc4 = (tid & 3) << 2;             // chunk base (0,4,8,12)
    const __half* Bk = TRANSB ? nullptr : (B + (size_t)bk * ldb + (size_t)bx * 128);

    auto issue = [&](int kt, int s) {
        uint32_t dA = smBase + s * STAGE;
        uint32_t dB = dA + A_BYTES;
        const __half* a = Arow + kt * 64;
        #pragma unroll
        for (int j = 0; j < 4; j++) {
            int ch = sc4 + j;
            cpa16(dA + (uint32_t)(sr * 128 + ((ch ^ (sr & 7)) << 4)), a + ch * 8);
        }
        if (TRANSB) {
            const __half* b = Brow + kt * 64;
            #pragma unroll
            for (int j = 0; j < 4; j++) {
                int ch = sc4 + j;
                cpa16(dB + (uint32_t)(sr * 128 + ((ch ^ (sr & 7)) << 4)), b + ch * 8);
            }
        } else {
            const __half* b = Bk + (size_t)kt * 64 * ldb;
            #pragma unroll
            for (int j = 0; j < 4; j++) {
                int ch = bc4 + j;
                cpa16(dB + (uint32_t)(bk * 256 + ((ch ^ (bk & 7)) << 4)), b + ch * 8);
            }
        }
        CP_COMMIT();
    };

    float acc[4][4][4];
    #pragma unroll
    for (int i = 0; i < 4; i++)
        #pragma unroll
        for (int j = 0; j < 4; j++)
            #pragma unroll
            for (int q = 0; q < 4; q++) acc[i][j][q] = 0.f;

    auto compute = [&](int s) {
        const uint32_t AbA = smBase + s * STAGE;
        const uint32_t BbA = AbA + A_BYTES;
        #pragma unroll
        for (int ks = 0; ks < 4; ks++) {        // four k16 steps in a 64-k tile
            uint32_t a[4][4], b[4][2];
            uint32_t aC = (uint32_t)((((ks << 1) + aSel) ^ lxor) << 4);
            #pragma unroll
            for (int mt = 0; mt < 4; mt++)
                ldsm4(a[mt], AbA + aBase + mt * 2048 + aC);
            if (TRANSB) {
                uint32_t bC = (uint32_t)((((ks << 1) + bSel) ^ lxor) << 4);
                ldsm4(&b[0][0], BbA + bBase + bC);
                ldsm4(&b[2][0], BbA + bBase + 2048 + bC);
            } else {
                uint32_t kRow = (uint32_t)(ks * 16 + tKL) * 256;
                ldsm4t(&b[0][0], BbA + kRow + (uint32_t)(((tNBase + 0) ^ lxor) << 4));
                ldsm4t(&b[2][0], BbA + kRow + (uint32_t)(((tNBase + 2) ^ lxor) << 4));
            }
            #pragma unroll
            for (int mt = 0; mt < 4; mt++)
                #pragma unroll
                for (int nt = 0; nt < 4; nt++)
                    mma_f16(acc[mt][nt], a[mt], b[nt]);
        }
    };

    int ktiles = K >> 6;               // always >= 2 here
    issue(0, 0);
    issue(1, 1);

    for (int kt = 0; kt < ktiles; kt++) {
        int buf = kt % NSTAGE;
        if (kt + 1 < ktiles) { CP_WAIT(1); } else { CP_WAIT(0); }
        __syncthreads();
        compute(buf);
        if (kt + 2 < ktiles) issue(kt + 2, (kt + 2) % NSTAGE);
    }

    // epilogue
    #pragma unroll
    for (int mt = 0; mt < 4; mt++) {
        #pragma unroll
        for (int half = 0; half < 2; half++) {
            int r = by * 128 + wm * 64 + mt * 16 + lr + 8 * half;
            #pragma unroll
            for (int nt = 0; nt < 4; nt++) {
                int cc = bx * 128 + wn * 32 + nt * 8 + 2 * lc;
                float2 v = make_float2(acc[mt][nt][2 * half], acc[mt][nt][2 * half + 1]);
                if (bias) {
                    float2 bb = *(const float2*)&bias[cc];
                    v.x += bb.x; v.y += bb.y;
                }
                if (flags & GF_GELU) {
                    v.x = 0.5f * v.x * (1.0f + erff(v.x * 0.70710678118654752f));
                    v.y = 0.5f * v.y * (1.0f + erff(v.y * 0.70710678118654752f));
                }
                if (flags & GF_HALF) {
                    __half2 hv = __floats2half2_rn(v.x, v.y);
                    *(__half2*)((__half*)Cv + (size_t)r * ldc + cc) = hv;
                } else {
                    float* crow = (float*)Cv + (size_t)r * ldc;
                    if (flags & GF_ADDC) {
                        float2 o = *(const float2*)&crow[cc];
                        v.x += o.x; v.y += o.y;
                    }
                    *(float2*)&crow[cc] = v;
                }
            }
        }
    }
}

// ---------------- generic batched GEMM kernel ---------------------------------------
template<bool TRANSB>
__global__ void __launch_bounds__(256, 2)
hmma_gemm(const __half* __restrict__ A, const __half* __restrict__ B,
          void* __restrict__ C, const float* __restrict__ bias,
          int K, int lda, int ldb, int ldc,
          long sAb, long sAh, long sBb, long sBh, long sCb, long sCh,
          long sBiash, int nH, int flags) {
    int bx = blockIdx.x, by = blockIdx.y;
    if ((flags & GF_CAUSAL) && bx > by) return;
    if (flags & GF_KLIM) K = min(K, (by + 1) * 128);

    int z  = blockIdx.z;
    int zb = z / nH, zh = z % nH;
    A += (size_t)zb * sAb + (size_t)zh * sAh;
    B += (size_t)zb * sBb + (size_t)zh * sBh;
    if (flags & GF_HALF) C = (void*)((__half*)C + (size_t)zb * sCb + (size_t)zh * sCh);
    else                 C = (void*)((float*)C + (size_t)zb * sCb + (size_t)zh * sCh);
    if (bias) bias += (size_t)zh * sBiash;

    gemm_body<TRANSB>(A, B, C, bias, K, lda, ldb, ldc, bx, by, flags);
}

// ---------------- fused QKV kernel (z = 0..3*H-1, sel = z/H) -------------------------
__global__ void __launch_bounds__(256, 2)
qkv_gemm(const __half* __restrict__ A,
         const __half* __restrict__ Wq, const __half* __restrict__ Wk, const __half* __restrict__ Wv,
         const float* __restrict__ bq, const float* __restrict__ bk, const float* __restrict__ bv,
         __half* __restrict__ Cq, __half* __restrict__ Ck, __half* __restrict__ Cv) {
    int z = blockIdx.z;
    int sel = z >> 2;        // H_ == 4
    int zh  = z & 3;
    const __half* W = (sel == 0) ? Wq : (sel == 1) ? Wk : Wv;
    const float* bb = (sel == 0) ? bq : (sel == 1) ? bk : bv;
    __half* C = (sel == 0) ? Cq : (sel == 1) ? Ck : Cv;
    W  += (size_t)zh * D_ * D_;
    bb += (size_t)zh * D_;
    C  += (size_t)zh * (size_t)M_ * D_;
    gemm_body<false>(A, W, (void*)C, bb, D_, D_, D_, D_, blockIdx.x, blockIdx.y, GF_HALF);
}

// ---------------- host-side launcher -------------------------------------------------
static void launch_gemm(bool transB, const __half* A, const __half* B, void* C,
                        const float* bias, int M, int N, int K,
                        int lda, int ldb, int ldc,
                        long sAb, long sAh, long sBb, long sBh,
                        long sCb, long sCh, long sBiash,
                        int nB, int nH, int flags) {
    dim3 grid(N / 128, M / 128, nB * nH);
    if (transB)
        hmma_gemm<true><<<grid, 256, SMEM_REQ>>>(A, B, C, bias, K, lda, ldb, ldc,
                                                 sAb, sAh, sBb, sBh, sCb, sCh, sBiash, nH, flags);
    else
        hmma_gemm<false><<<grid, 256, SMEM_REQ>>>(A, B, C, bias, K, lda, ldb, ldc,
                                                  sAb, sAh, sBb, sBh, sCb, sCh, sBiash, nH, flags);
}

static void launch_f2h(const float* s, __half* d, long n) {
    int blocks = (int)((n + 2047) / 2048);
    f2h_kernel<<<blocks, 256>>>(s, d, (int)n);
}

extern "C" void kernel_launch(void* const* d_in, const int* in_sizes, int n_in,
                              void* d_out, int out_size) {
    const int*   x         = (const int*)  d_in[0];
    const float* token_emb = (const float*)d_in[1];
    const float* Wq   = (const float*)d_in[2];
    const float* bq   = (const float*)d_in[3];
    const float* Wk   = (const float*)d_in[4];
    const float* bk   = (const float*)d_in[5];
    const float* Wv   = (const float*)d_in[6];
    const float* bv   = (const float*)d_in[7];
    const float* Wo   = (const float*)d_in[8];
    const float* bo   = (const float*)d_in[9];
    const float* ln1g = (const float*)d_in[10];
    const float* ln1b = (const float*)d_in[11];
    const float* ln2g = (const float*)d_in[12];
    const float* ln2b = (const float*)d_in[13];
    const float* W1   = (const float*)d_in[14];
    const float* b1   = (const float*)d_in[15];
    const float* W2   = (const float*)d_in[16];
    const float* b2   = (const float*)d_in[17];
    const float* flng = (const float*)d_in[18];
    const float* flnb = (const float*)d_in[19];
    const float* Wout = (const float*)d_in[20];
    float* out = (float*)d_out;

    cudaFuncSetAttribute(hmma_gemm<false>, cudaFuncAttributeMaxDynamicSharedMemorySize, SMEM_REQ);
    cudaFuncSetAttribute(hmma_gemm<true>,  cudaFuncAttributeMaxDynamicSharedMemorySize, SMEM_REQ);
    cudaFuncSetAttribute(qkv_gemm,         cudaFuncAttributeMaxDynamicSharedMemorySize, SMEM_REQ);
    cudaFuncSetAttribute(logsoftmax_kernel, cudaFuncAttributeMaxDynamicSharedMemorySize, V_ * 4);

    float *ph, *ps;
    __half *pxn, *pq, *pk, *pv, *pa, *py, *pff;
    __half *wq, *wk, *wv, *wo, *w1, *w2, *wout;
    cudaGetSymbolAddress((void**)&ph,  g_h);
    cudaGetSymbolAddress((void**)&ps,  g_s);
    cudaGetSymbolAddress((void**)&pxn, g_xn);
    cudaGetSymbolAddress((void**)&pq,  g_q);
    cudaGetSymbolAddress((void**)&pk,  g_k);
    cudaGetSymbolAddress((void**)&pv,  g_v);
    cudaGetSymbolAddress((void**)&pa,  g_a);
    cudaGetSymbolAddress((void**)&py,  g_y);
    cudaGetSymbolAddress((void**)&pff, g_ff);
    cudaGetSymbolAddress((void**)&wq,  g_wq);
    cudaGetSymbolAddress((void**)&wk,  g_wk);
    cudaGetSymbolAddress((void**)&wv,  g_wv);
    cudaGetSymbolAddress((void**)&wo,  g_wo);
    cudaGetSymbolAddress((void**)&w1,  g_w1);
    cudaGetSymbolAddress((void**)&w2,  g_w2);
    cudaGetSymbolAddress((void**)&wout, g_wout);

    // weight conversion (fp32 -> fp16)
    launch_f2h(Wq,   wq,   (long)L_ * H_ * D_ * D_);
    launch_f2h(Wk,   wk,   (long)L_ * H_ * D_ * D_);
    launch_f2h(Wv,   wv,   (long)L_ * H_ * D_ * D_);
    launch_f2h(Wo,   wo,   (long)L_ * H_ * D_ * D_);
    launch_f2h(W1,   w1,   (long)L_ * D_ * DFF_);
    launch_f2h(W2,   w2,   (long)L_ * DFF_ * D_);
    launch_f2h(Wout, wout, (long)D_ * V_);

    embed_kernel<<<M_, 256>>>(x, token_emb, ph);

    for (int l = 0; l < L_; l++) {
        layernorm_kernel<<<M_, 256>>>(ph, pxn, ln1g + (size_t)l * D_, ln1b + (size_t)l * D_);

        const long wOff = (long)l * H_ * D_ * D_;
        const long bOff = (long)l * H_ * D_;
        {
            dim3 grid(D_ / 128, M_ / 128, 3 * H_);
            qkv_gemm<<<grid, 256, SMEM_REQ>>>(pxn,
                wq + wOff, wk + wOff, wv + wOff,
                bq + bOff, bk + bOff, bv + bOff,
                pq, pk, pv);
        }

        // S = Q @ K^T per (b,h): K matrix is [T,D] = n-major
        launch_gemm(true, pq, pk, ps, nullptr,
                    T_, T_, D_, D_, D_, T_,
                    (long)T_ * D_, (long)M_ * D_,
                    (long)T_ * D_, (long)M_ * D_,
                    (long)H_ * T_ * T_, (long)T_ * T_,
                    0, B_, H_, GF_CAUSAL);

        attn_softmax_kernel<<<B_ * H_ * T_, 256>>>(ps, pa);

        // y = A @ V per (b,h), fp16 out
        launch_gemm(false, pa, pv, py, nullptr,
                    T_, D_, T_, T_, D_, H_ * D_,
                    (long)H_ * T_ * T_, (long)T_ * T_,
                    (long)T_ * D_, (long)M_ * D_,
                    (long)T_ * H_ * D_, (long)D_,
                    0, B_, H_, GF_KLIM | GF_HALF);

        // h += y @ Wo + bo (fp32 residual)
        launch_gemm(false, py, wo + wOff, ph, bo + (long)l * D_,
                    M_, D_, H_ * D_, H_ * D_, D_, D_,
                    0, 0, 0, 0, 0, 0, 0, 1, 1, GF_ADDC);

        layernorm_kernel<<<M_, 256>>>(ph, pxn, ln2g + (size_t)l * D_, ln2b + (size_t)l * D_);

        // ff = gelu(xn @ W1 + b1), fp16 out
        launch_gemm(false, pxn, w1 + (long)l * D_ * DFF_, pff, b1 + (long)l * DFF_,
                    M_, DFF_, D_, D_, DFF_, DFF_,
                    0, 0, 0, 0, 0, 0, 0, 1, 1, GF_GELU | GF_HALF);

        // h += ff @ W2 + b2
        launch_gemm(false, pff, w2 + (long)l * DFF_ * D_, ph, b2 + (long)l * D_,
                    M_, D_, DFF_, DFF_, D_, D_,
                    0, 0, 0, 0, 0, 0, 0, 1, 1, GF_ADDC);
    }

    layernorm_kernel<<<M_, 256>>>(ph, pxn, flng, flnb);

    // logits = xn @ Wout (fp32, straight into d_out)
    launch_gemm(false, pxn, wout, out, nullptr,
                M_, V_, D_, D_, V_, V_,
                0, 0, 0, 0, 0, 0, 0, 1, 1, 0);

    logsoftmax_kernel<<<M_, 256, V_ * 4>>>(out);
}

// round 9
// speedup vs baseline: 6.8242x; 1.0147x over previous
#include <cuda_runtime.h>
#include <cuda_fp16.h>
#include <cstdint>
#include <math.h>

#define L_   4
#define H_   4
#define B_   2
#define T_   1024
#define D_   1024
#define DFF_ 4096
#define V_   32000
#define M_   (B_*T_)   // 2048 tokens

// ---------------- scratch (static device globals; no allocs allowed) ----------
__device__ float  g_h [M_*D_];          // residual (fp32)
__device__ float  g_s [B_*H_*T_*T_];    // attention scores (fp32)
__device__ float  g_part[4*M_*D_];      // split-K partials (fp32)
__device__ __half g_xn[M_*D_];          // LN output (fp16)
__device__ __half g_q [H_*M_*D_];
__device__ __half g_k [H_*M_*D_];
__device__ __half g_v [H_*M_*D_];
__device__ __half g_a [B_*H_*T_*T_];    // softmax probs (fp16)
__device__ __half g_y [M_*H_*D_];
__device__ __half g_ff[M_*DFF_];
// fp16 weight mirrors
__device__ __half g_wq[L_*H_*D_*D_];
__device__ __half g_wk[L_*H_*D_*D_];
__device__ __half g_wv[L_*H_*D_*D_];
__device__ __half g_wo[L_*H_*D_*D_];
__device__ __half g_w1[L_*D_*DFF_];
__device__ __half g_w2[L_*DFF_*D_];
__device__ __half g_wout[D_*V_];

// ---------------- helpers -------------------------------------------------------
__device__ __forceinline__ uint32_t smem_u32(const void* p) {
    uint32_t a;
    asm("{ .reg .u64 t; cvta.to.shared.u64 t, %1; cvt.u32.u64 %0, t; }" : "=r"(a) : "l"(p));
    return a;
}
__device__ __forceinline__ void cpa16(uint32_t dst, const void* src) {
    asm volatile("cp.async.cg.shared.global [%0], [%1], 16;" :: "r"(dst), "l"(src) : "memory");
}
#define CP_COMMIT() asm volatile("cp.async.commit_group;" ::: "memory")
#define CP_WAIT(n)  asm volatile("cp.async.wait_group %0;" :: "n"(n) : "memory")

__device__ __forceinline__ void mma_f16(float* c, const uint32_t* a, const uint32_t* b) {
    asm volatile("mma.sync.aligned.m16n8k16.row.col.f32.f16.f16.f32 "
        "{%0,%1,%2,%3}, {%4,%5,%6,%7}, {%8,%9}, {%0,%1,%2,%3};"
        : "+f"(c[0]), "+f"(c[1]), "+f"(c[2]), "+f"(c[3])
        : "r"(a[0]), "r"(a[1]), "r"(a[2]), "r"(a[3]), "r"(b[0]), "r"(b[1]));
}
__device__ __forceinline__ void ldsm4(uint32_t* r, uint32_t addr) {
    asm volatile("ldmatrix.sync.aligned.m8n8.x4.shared.b16 {%0,%1,%2,%3}, [%4];"
        : "=r"(r[0]), "=r"(r[1]), "=r"(r[2]), "=r"(r[3]) : "r"(addr));
}
__device__ __forceinline__ void ldsm4t(uint32_t* r, uint32_t addr) {
    asm volatile("ldmatrix.sync.aligned.m8n8.x4.trans.shared.b16 {%0,%1,%2,%3}, [%4];"
        : "=r"(r[0]), "=r"(r[1]), "=r"(r[2]), "=r"(r[3]) : "r"(addr));
}

// ---------------- fast exp on the FMA pipe --------------------------------------
__device__ __forceinline__ float fexp(float x) {
    x = fmaxf(x, -80.f);
    float z = x * 1.4426950408889634f;
    float y = z + 12582912.0f;
    float n = y - 12582912.0f;
    float t = fmaf(n, -0.6931471805599453f, x);
    float p =             0.008333333f;
    p = fmaf(p, t, 0.041666668f);
    p = fmaf(p, t, 0.16666667f);
    p = fmaf(p, t, 0.5f);
    p = fmaf(p, t, 1.0f);
    p = fmaf(p, t, 1.0f);
    int e = __float_as_int(y) - 0x4B400000;
    return p * __int_as_float((127 + e) << 23);
}

// ---------------- block reductions ----------------------------------------------
__device__ __forceinline__ float blockReduceSum(float v) {
    __shared__ float sh[9];
    int lane = threadIdx.x & 31, w = threadIdx.x >> 5;
    #pragma unroll
    for (int o = 16; o; o >>= 1) v += __shfl_xor_sync(0xffffffffu, v, o);
    if (lane == 0) sh[w] = v;
    __syncthreads();
    if (threadIdx.x == 0) {
        float s = 0.f;
        #pragma unroll
        for (int i = 0; i < 8; i++) s += sh[i];
        sh[8] = s;
    }
    __syncthreads();
    float r = sh[8];
    __syncthreads();
    return r;
}
__device__ __forceinline__ float blockReduceMax(float v) {
    __shared__ float sh[9];
    int lane = threadIdx.x & 31, w = threadIdx.x >> 5;
    #pragma unroll
    for (int o = 16; o; o >>= 1) v = fmaxf(v, __shfl_xor_sync(0xffffffffu, v, o));
    if (lane == 0) sh[w] = v;
    __syncthreads();
    if (threadIdx.x == 0) {
        float s = sh[0];
        #pragma unroll
        for (int i = 1; i < 8; i++) s = fmaxf(s, sh[i]);
        sh[8] = s;
    }
    __syncthreads();
    float r = sh[8];
    __syncthreads();
    return r;
}

// ---------------- fp32 -> fp16 convert ------------------------------------------
__global__ void f2h_kernel(const float* __restrict__ s, __half* __restrict__ d, int n) {
    int i = (blockIdx.x * blockDim.x + threadIdx.x) * 8;
    if (i >= n) return;
    float4 v0 = *(const float4*)(s + i);
    float4 v1 = *(const float4*)(s + i + 4);
    __half2 h0 = __floats2half2_rn(v0.x, v0.y);
    __half2 h1 = __floats2half2_rn(v0.z, v0.w);
    __half2 h2 = __floats2half2_rn(v1.x, v1.y);
    __half2 h3 = __floats2half2_rn(v1.z, v1.w);
    uint4 u;
    u.x = *(uint32_t*)&h0; u.y = *(uint32_t*)&h1;
    u.z = *(uint32_t*)&h2; u.w = *(uint32_t*)&h3;
    *(uint4*)(d + i) = u;
}

// ---------------- split-K reduce: h += (p0+p1+p2+p3) + bias ----------------------
__global__ void reduce4_add(float* __restrict__ h, const float* __restrict__ part,
                            const float* __restrict__ bias) {
    int m = blockIdx.x;
    int c = threadIdx.x * 4;
    const float* p = part + (size_t)m * D_ + c;
    float4 p0 = *(const float4*)(p);
    float4 p1 = *(const float4*)(p + (size_t)M_ * D_);
    float4 p2 = *(const float4*)(p + 2 * (size_t)M_ * D_);
    float4 p3 = *(const float4*)(p + 3 * (size_t)M_ * D_);
    float4 bb = *(const float4*)(bias + c);
    float4 hv = *(float4*)(h + (size_t)m * D_ + c);
    hv.x += p0.x + p1.x + p2.x + p3.x + bb.x;
    hv.y += p0.y + p1.y + p2.y + p3.y + bb.y;
    hv.z += p0.z + p1.z + p2.z + p3.z + bb.z;
    hv.w += p0.w + p1.w + p2.w + p3.w + bb.w;
    *(float4*)(h + (size_t)m * D_ + c) = hv;
}

// ---------------- embedding ------------------------------------------------------
__global__ void embed_kernel(const int* __restrict__ x,
                             const float* __restrict__ emb,
                             float* __restrict__ h) {
    int m = blockIdx.x;
    int t = m % T_;
    int tok = x[m];
    const float* erow = emb + (size_t)tok * D_;
    float* hrow = h + (size_t)m * D_;
    for (int d = threadIdx.x; d < D_; d += blockDim.x) {
        int i = d >> 1;
        float denom = powf(10000.f, (2.f * (float)i) / (float)D_);
        float ang = (float)t / denom;
        float pe = (d & 1) ? cosf(ang) : sinf(ang);
        hrow[d] = erow[d] + pe;
    }
}

// ---------------- layernorm (fp32 in, fp16 out) ----------------------------------
__global__ void layernorm_kernel(const float* __restrict__ in,
                                 __half* __restrict__ out,
                                 const float* __restrict__ g,
                                 const float* __restrict__ b) {
    int m = blockIdx.x;
    int tid = threadIdx.x;
    const float4* x4 = (const float4*)(in + (size_t)m * D_);
    float4 v = x4[tid];
    float s = v.x + v.y + v.z + v.w;
    s = blockReduceSum(s);
    float mean = s * (1.0f / D_);
    float dx = v.x - mean, dy = v.y - mean, dz = v.z - mean, dw = v.w - mean;
    float q = dx*dx + dy*dy + dz*dz + dw*dw;
    q = blockReduceSum(q);
    float inv = rsqrtf(q * (1.0f / D_) + 1e-5f);
    float4 gg = ((const float4*)g)[tid];
    float4 bb = ((const float4*)b)[tid];
    __half2 h0 = __floats2half2_rn(dx * inv * gg.x + bb.x, dy * inv * gg.y + bb.y);
    __half2 h1 = __floats2half2_rn(dz * inv * gg.z + bb.z, dw * inv * gg.w + bb.w);
    uint2 u; u.x = *(uint32_t*)&h0; u.y = *(uint32_t*)&h1;
    *(uint2*)(out + (size_t)m * D_ + tid * 4) = u;
}

// ---------------- causal softmax (fp32 scores in, fp16 probs out) ----------------
__global__ void attn_softmax_kernel(const float* __restrict__ S, __half* __restrict__ A) {
    int r = blockIdx.x;            // 0 .. B*H*T-1
    int t = r % T_;
    int z = r / T_;
    const float* row = S + (size_t)z * T_ * T_ + (size_t)t * T_;
    __half* arow = A + (size_t)z * T_ * T_ + (size_t)t * T_;
    const float scale = 0.03125f;  // 1/sqrt(1024)
    int tid = threadIdx.x;
    float v[4];
    #pragma unroll
    for (int i = 0; i < 4; i++) {
        int s = tid + 256 * i;
        v[i] = (s <= t) ? row[s] * scale : -INFINITY;
    }
    float lmax = fmaxf(fmaxf(v[0], v[1]), fmaxf(v[2], v[3]));
    float mx = blockReduceMax(lmax);
    float e[4]; float lsum = 0.f;
    #pragma unroll
    for (int i = 0; i < 4; i++) {
        int s = tid + 256 * i;
        e[i] = (s <= t) ? fexp(v[i] - mx) : 0.f;
        lsum += e[i];
    }
    float sum = blockReduceSum(lsum);
    float invs = 1.0f / sum;
    #pragma unroll
    for (int i = 0; i < 4; i++) {
        int s = tid + 256 * i;
        arow[s] = __float2half(e[i] * invs);
    }
}

// ---------------- final log-softmax: row cached in SMEM --------------------------
__global__ void logsoftmax_kernel(float* __restrict__ out) {
    extern __shared__ float sv[];
    float* row = out + (size_t)blockIdx.x * V_;
    int tid = threadIdx.x;
    float lmax = -INFINITY;
    for (int i = tid * 4; i < V_; i += 1024) {
        float4 v = *(const float4*)&row[i];
        *(float4*)&sv[i] = v;
        lmax = fmaxf(lmax, fmaxf(fmaxf(v.x, v.y), fmaxf(v.z, v.w)));
    }
    float mx = blockReduceMax(lmax);
    float lsum = 0.f;
    for (int i = tid; i < V_; i += 256) lsum += fexp(sv[i] - mx);
    float sum = blockReduceSum(lsum);
    float lse = logf(sum) + mx;
    for (int i = tid * 4; i < V_; i += 1024) {
        float4 v = *(const float4*)&sv[i];
        v.x -= lse; v.y -= lse; v.z -= lse; v.w -= lse;
        *(float4*)&row[i] = v;
    }
}

// ---------------- fp16 HMMA GEMM body: m16n8k16, 3-stage cp.async ----------------
// CTA 128x128, K-tile 64 halves (128B rows), 8 warps (2m x 4n), warp 64x32.
// A (and B when TRANSB): [row][64 halves], 16B-chunk XOR swizzle ch ^= (row&7).
// B !TRANSB: [k][128 halves] (256B rows, 16 chunks), ch ^= (k&7); ldmatrix.trans.
#define GF_ADDC   1
#define GF_GELU   2
#define GF_CAUSAL 4
#define GF_KLIM   8
#define GF_HALF   16

#define A_BYTES   16384                 // 128 x 128B
#define B_BYTES   16384                 // both layouts
#define STAGE     (A_BYTES + B_BYTES)   // 32768
#define NSTAGE    3
#define SMEM_REQ  (NSTAGE * STAGE)      // 98304

template<bool TRANSB>
__device__ __forceinline__ void gemm_body(
        const __half* __restrict__ A, const __half* __restrict__ B,
        void* __restrict__ Cv, const float* __restrict__ bias,
        int K, int lda, int ldb, int ldc, int bx, int by, int flags) {
    extern __shared__ char sm[];
    const uint32_t smBase = smem_u32(sm);

    const int tid = threadIdx.x;
    const int wid = tid >> 5, lane = tid & 31;
    const int lr = lane >> 2, lc = lane & 3;
    const int wm = wid & 1, wn = wid >> 1;      // warp tile: rows wm*64, cols wn*32
    const int lxor = lane & 7;                  // XOR term (row&7 == lane&7 everywhere)

    // ldmatrix lane maps
    const int aRowL = ((lane >> 3) & 1) * 8 + (lane & 7);
    const int aSel  = (lane >> 4) & 1;                    // +8 k  (chunk +1)
    const uint32_t aBase = (uint32_t)((wm * 64 + aRowL) * 128);
    // B TRANSB (n-major rows)
    const int bRowL = ((lane >> 4) & 1) * 8 + (lane & 7);
    const int bSel  = (lane >> 3) & 1;
    const uint32_t bBase = (uint32_t)((wn * 32 + bRowL) * 128);
    // B !TRANSB (k-major rows, ldmatrix.trans)
    const int tKL   = ((lane >> 3) & 1) * 8 + (lane & 7); // k within 16-step
    const int tNSel = (lane >> 4) & 1;                    // +8 n (chunk +1)
    const int tNBase = wn * 4 + tNSel;                    // n-chunk base

    // staging maps
    const int sr  = tid >> 1;                   // A/B-trans row
    const int sc4 = (tid & 1) << 2;             // chunk base (0 or 4)
    const __half* Arow = A + (size_t)(by * 128 + sr) * lda;
    const __half* Brow = TRANSB ? (B + (size_t)(bx * 128 + sr) * ldb) : nullptr;
    const int bk  = tid >> 2;                   // !TRANSB: k row (0..63)
    const int bc4 = (tid & 3) << 2;             // chunk base (0,4,8,12)
    const __half* Bk = TRANSB ? nullptr : (B + (size_t)bk * ldb + (size_t)bx * 128);

    auto issue = [&](int kt, int s) {
        uint32_t dA = smBase + s * STAGE;
        uint32_t dB = dA + A_BYTES;
        const __half* a = Arow + kt * 64;
        #pragma unroll
        for (int j = 0; j < 4; j++) {
            int ch = sc4 + j;
            cpa16(dA + (uint32_t)(sr * 128 + ((ch ^ (sr & 7)) << 4)), a + ch * 8);
        }
        if (TRANSB) {
            const __half* b = Brow + kt * 64;
            #pragma unroll
            for (int j = 0; j < 4; j++) {
                int ch = sc4 + j;
                cpa16(dB + (uint32_t)(sr * 128 + ((ch ^ (sr & 7)) << 4)), b + ch * 8);
            }
        } else {
            const __half* b = Bk + (size_t)kt * 64 * ldb;
            #pragma unroll
            for (int j = 0; j < 4; j++) {
                int ch = bc4 + j;
                cpa16(dB + (uint32_t)(bk * 256 + ((ch ^ (bk & 7)) << 4)), b + ch * 8);
            }
        }
        CP_COMMIT();
    };

    float acc[4][4][4];
    #pragma unroll
    for (int i = 0; i < 4; i++)
        #pragma unroll
        for (int j = 0; j < 4; j++)
            #pragma unroll
            for (int q = 0; q < 4; q++) acc[i][j][q] = 0.f;

    auto compute = [&](int s) {
        const uint32_t AbA = smBase + s * STAGE;
        const uint32_t BbA = AbA + A_BYTES;
        #pragma unroll
        for (int ks = 0; ks < 4; ks++) {        // four k16 steps in a 64-k tile
            uint32_t a[4][4], b[4][2];
            uint32_t aC = (uint32_t)((((ks << 1) + aSel) ^ lxor) << 4);
            #pragma unroll
            for (int mt = 0; mt < 4; mt++)
                ldsm4(a[mt], AbA + aBase + mt * 2048 + aC);
            if (TRANSB) {
                uint32_t bC = (uint32_t)((((ks << 1) + bSel) ^ lxor) << 4);
                ldsm4(&b[0][0], BbA + bBase + bC);
                ldsm4(&b[2][0], BbA + bBase + 2048 + bC);
            } else {
                uint32_t kRow = (uint32_t)(ks * 16 + tKL) * 256;
                ldsm4t(&b[0][0], BbA + kRow + (uint32_t)(((tNBase + 0) ^ lxor) << 4));
                ldsm4t(&b[2][0], BbA + kRow + (uint32_t)(((tNBase + 2) ^ lxor) << 4));
            }
            #pragma unroll
            for (int mt = 0; mt < 4; mt++)
                #pragma unroll
                for (int nt = 0; nt < 4; nt++)
                    mma_f16(acc[mt][nt], a[mt], b[nt]);
        }
    };

    int ktiles = K >> 6;               // always >= 2 here
    issue(0, 0);
    issue(1, 1);

    for (int kt = 0; kt < ktiles; kt++) {
        int buf = kt % NSTAGE;
        if (kt + 1 < ktiles) { CP_WAIT(1); } else { CP_WAIT(0); }
        __syncthreads();
        compute(buf);
        if (kt + 2 < ktiles) issue(kt + 2, (kt + 2) % NSTAGE);
    }

    // epilogue
    #pragma unroll
    for (int mt = 0; mt < 4; mt++) {
        #pragma unroll
        for (int half = 0; half < 2; half++) {
            int r = by * 128 + wm * 64 + mt * 16 + lr + 8 * half;
            #pragma unroll
            for (int nt = 0; nt < 4; nt++) {
                int cc = bx * 128 + wn * 32 + nt * 8 + 2 * lc;
                float2 v = make_float2(acc[mt][nt][2 * half], acc[mt][nt][2 * half + 1]);
                if (bias) {
                    float2 bb = *(const float2*)&bias[cc];
                    v.x += bb.x; v.y += bb.y;
                }
                if (flags & GF_GELU) {
                    v.x = 0.5f * v.x * (1.0f + erff(v.x * 0.70710678118654752f));
                    v.y = 0.5f * v.y * (1.0f + erff(v.y * 0.70710678118654752f));
                }
                if (flags & GF_HALF) {
                    __half2 hv = __floats2half2_rn(v.x, v.y);
                    *(__half2*)((__half*)Cv + (size_t)r * ldc + cc) = hv;
                } else {
                    float* crow = (float*)Cv + (size_t)r * ldc;
                    if (flags & GF_ADDC) {
                        float2 o = *(const float2*)&crow[cc];
                        v.x += o.x; v.y += o.y;
                    }
                    *(float2*)&crow[cc] = v;
                }
            }
        }
    }
}

// ---------------- generic batched GEMM kernel ---------------------------------------
template<bool TRANSB>
__global__ void __launch_bounds__(256, 2)
hmma_gemm(const __half* __restrict__ A, const __half* __restrict__ B,
          void* __restrict__ C, const float* __restrict__ bias,
          int K, int lda, int ldb, int ldc,
          long sAb, long sAh, long sBb, long sBh, long sCb, long sCh,
          long sBiash, int nH, int flags) {
    int bx = blockIdx.x, by = blockIdx.y;
    if ((flags & GF_CAUSAL) && bx > by) return;
    if (flags & GF_KLIM) K = min(K, (by + 1) * 128);

    int z  = blockIdx.z;
    int zb = z / nH, zh = z % nH;
    A += (size_t)zb * sAb + (size_t)zh * sAh;
    B += (size_t)zb * sBb + (size_t)zh * sBh;
    if (flags & GF_HALF) C = (void*)((__half*)C + (size_t)zb * sCb + (size_t)zh * sCh);
    else                 C = (void*)((float*)C + (size_t)zb * sCb + (size_t)zh * sCh);
    if (bias) bias += (size_t)zh * sBiash;

    gemm_body<TRANSB>(A, B, C, bias, K, lda, ldb, ldc, bx, by, flags);
}

// ---------------- fused QKV kernel (z = 0..3*H-1, sel = z/H) -------------------------
__global__ void __launch_bounds__(256, 2)
qkv_gemm(const __half* __restrict__ A,
         const __half* __restrict__ Wq, const __half* __restrict__ Wk, const __half* __restrict__ Wv,
         const float* __restrict__ bq, const float* __restrict__ bk, const float* __restrict__ bv,
         __half* __restrict__ Cq, __half* __restrict__ Ck, __half* __restrict__ Cv) {
    int z = blockIdx.z;
    int sel = z >> 2;        // H_ == 4
    int zh  = z & 3;
    const __half* W = (sel == 0) ? Wq : (sel == 1) ? Wk : Wv;
    const float* bb = (sel == 0) ? bq : (sel == 1) ? bk : bv;
    __half* C = (sel == 0) ? Cq : (sel == 1) ? Ck : Cv;
    W  += (size_t)zh * D_ * D_;
    bb += (size_t)zh * D_;
    C  += (size_t)zh * (size_t)M_ * D_;
    gemm_body<false>(A, W, (void*)C, bb, D_, D_, D_, D_, blockIdx.x, blockIdx.y, GF_HALF);
}

// ---------------- host-side launcher -------------------------------------------------
static void launch_gemm(bool transB, const __half* A, const __half* B, void* C,
                        const float* bias, int M, int N, int K,
                        int lda, int ldb, int ldc,
                        long sAb, long sAh, long sBb, long sBh,
                        long sCb, long sCh, long sBiash,
                        int nB, int nH, int flags) {
    dim3 grid(N / 128, M / 128, nB * nH);
    if (transB)
        hmma_gemm<true><<<grid, 256, SMEM_REQ>>>(A, B, C, bias, K, lda, ldb, ldc,
                                                 sAb, sAh, sBb, sBh, sCb, sCh, sBiash, nH, flags);
    else
        hmma_gemm<false><<<grid, 256, SMEM_REQ>>>(A, B, C, bias, K, lda, ldb, ldc,
                                                  sAb, sAh, sBb, sBh, sCb, sCh, sBiash, nH, flags);
}

static void launch_f2h(const float* s, __half* d, long n) {
    int blocks = (int)((n + 2047) / 2048);
    f2h_kernel<<<blocks, 256>>>(s, d, (int)n);
}

extern "C" void kernel_launch(void* const* d_in, const int* in_sizes, int n_in,
                              void* d_out, int out_size) {
    const int*   x         = (const int*)  d_in[0];
    const float* token_emb = (const float*)d_in[1];
    const float* Wq   = (const float*)d_in[2];
    const float* bq   = (const float*)d_in[3];
    const float* Wk   = (const float*)d_in[4];
    const float* bk   = (const float*)d_in[5];
    const float* Wv   = (const float*)d_in[6];
    const float* bv   = (const float*)d_in[7];
    const float* Wo   = (const float*)d_in[8];
    const float* bo   = (const float*)d_in[9];
    const float* ln1g = (const float*)d_in[10];
    const float* ln1b = (const float*)d_in[11];
    const float* ln2g = (const float*)d_in[12];
    const float* ln2b = (const float*)d_in[13];
    const float* W1   = (const float*)d_in[14];
    const float* b1   = (const float*)d_in[15];
    const float* W2   = (const float*)d_in[16];
    const float* b2   = (const float*)d_in[17];
    const float* flng = (const float*)d_in[18];
    const float* flnb = (const float*)d_in[19];
    const float* Wout = (const float*)d_in[20];
    float* out = (float*)d_out;

    cudaFuncSetAttribute(hmma_gemm<false>, cudaFuncAttributeMaxDynamicSharedMemorySize, SMEM_REQ);
    cudaFuncSetAttribute(hmma_gemm<true>,  cudaFuncAttributeMaxDynamicSharedMemorySize, SMEM_REQ);
    cudaFuncSetAttribute(qkv_gemm,         cudaFuncAttributeMaxDynamicSharedMemorySize, SMEM_REQ);
    cudaFuncSetAttribute(logsoftmax_kernel, cudaFuncAttributeMaxDynamicSharedMemorySize, V_ * 4);

    float *ph, *ps, *ppart;
    __half *pxn, *pq, *pk, *pv, *pa, *py, *pff;
    __half *wq, *wk, *wv, *wo, *w1, *w2, *wout;
    cudaGetSymbolAddress((void**)&ph,  g_h);
    cudaGetSymbolAddress((void**)&ps,  g_s);
    cudaGetSymbolAddress((void**)&ppart, g_part);
    cudaGetSymbolAddress((void**)&pxn, g_xn);
    cudaGetSymbolAddress((void**)&pq,  g_q);
    cudaGetSymbolAddress((void**)&pk,  g_k);
    cudaGetSymbolAddress((void**)&pv,  g_v);
    cudaGetSymbolAddress((void**)&pa,  g_a);
    cudaGetSymbolAddress((void**)&py,  g_y);
    cudaGetSymbolAddress((void**)&pff, g_ff);
    cudaGetSymbolAddress((void**)&wq,  g_wq);
    cudaGetSymbolAddress((void**)&wk,  g_wk);
    cudaGetSymbolAddress((void**)&wv,  g_wv);
    cudaGetSymbolAddress((void**)&wo,  g_wo);
    cudaGetSymbolAddress((void**)&w1,  g_w1);
    cudaGetSymbolAddress((void**)&w2,  g_w2);
    cudaGetSymbolAddress((void**)&wout, g_wout);

    // weight conversion (fp32 -> fp16)
    launch_f2h(Wq,   wq,   (long)L_ * H_ * D_ * D_);
    launch_f2h(Wk,   wk,   (long)L_ * H_ * D_ * D_);
    launch_f2h(Wv,   wv,   (long)L_ * H_ * D_ * D_);
    launch_f2h(Wo,   wo,   (long)L_ * H_ * D_ * D_);
    launch_f2h(W1,   w1,   (long)L_ * D_ * DFF_);
    launch_f2h(W2,   w2,   (long)L_ * DFF_ * D_);
    launch_f2h(Wout, wout, (long)D_ * V_);

    embed_kernel<<<M_, 256>>>(x, token_emb, ph);

    for (int l = 0; l < L_; l++) {
        layernorm_kernel<<<M_, 256>>>(ph, pxn, ln1g + (size_t)l * D_, ln1b + (size_t)l * D_);

        const long wOff = (long)l * H_ * D_ * D_;
        const long bOff = (long)l * H_ * D_;
        {
            dim3 grid(D_ / 128, M_ / 128, 3 * H_);
            qkv_gemm<<<grid, 256, SMEM_REQ>>>(pxn,
                wq + wOff, wk + wOff, wv + wOff,
                bq + bOff, bk + bOff, bv + bOff,
                pq, pk, pv);
        }

        // S = Q @ K^T per (b,h): K matrix is [T,D] = n-major
        launch_gemm(true, pq, pk, ps, nullptr,
                    T_, T_, D_, D_, D_, T_,
                    (long)T_ * D_, (long)M_ * D_,
                    (long)T_ * D_, (long)M_ * D_,
                    (long)H_ * T_ * T_, (long)T_ * T_,
                    0, B_, H_, GF_CAUSAL);

        attn_softmax_kernel<<<B_ * H_ * T_, 256>>>(ps, pa);

        // y = A @ V per (b,h), fp16 out
        launch_gemm(false, pa, pv, py, nullptr,
                    T_, D_, T_, T_, D_, H_ * D_,
                    (long)H_ * T_ * T_, (long)T_ * T_,
                    (long)T_ * D_, (long)M_ * D_,
                    (long)T_ * H_ * D_, (long)D_,
                    0, B_, H_, GF_KLIM | GF_HALF);

        // h += y @ Wo + bo : 4-way split-K into partials, then deterministic reduce
        launch_gemm(false, py, wo + wOff, ppart, nullptr,
                    M_, D_, D_ /*K slice*/, H_ * D_, D_, D_,
                    0, (long)D_,                     // A: k-offset within row
                    0, (long)D_ * D_,                // B: k-row offset
                    0, (long)M_ * D_,                // C: partial slab
                    0, 1, 4, 0);
        reduce4_add<<<M_, 256>>>(ph, ppart, bo + (long)l * D_);

        layernorm_kernel<<<M_, 256>>>(ph, pxn, ln2g + (size_t)l * D_, ln2b + (size_t)l * D_);

        // ff = gelu(xn @ W1 + b1), fp16 out
        launch_gemm(false, pxn, w1 + (long)l * D_ * DFF_, pff, b1 + (long)l * DFF_,
                    M_, DFF_, D_, D_, DFF_, DFF_,
                    0, 0, 0, 0, 0, 0, 0, 1, 1, GF_GELU | GF_HALF);

        // h += ff @ W2 + b2 : 4-way split-K (K=4096 -> 4 x 1024)
        launch_gemm(false, pff, w2 + (long)l * DFF_ * D_, ppart, nullptr,
                    M_, D_, D_ /*K slice*/, DFF_, D_, D_,
                    0, (long)D_,                     // A: k-offset within row (DFF row)
                    0, (long)D_ * D_,                // B: k-row offset
                    0, (long)M_ * D_,                // C: partial slab
                    0, 1, 4, 0);
        reduce4_add<<<M_, 256>>>(ph, ppart, b2 + (long)l * D_);

        // NOTE: A k-offset for W2 split is within DFF_-wide rows
        // (sAh = D_ elements = 1024 halves = exactly one K slice of 1024)
    }

    layernorm_kernel<<<M_, 256>>>(ph, pxn, flng, flnb);

    // logits = xn @ Wout (fp32, straight into d_out)
    launch_gemm(false, pxn, wout, out, nullptr,
                M_, V_, D_, D_, V_, V_,
                0, 0, 0, 0, 0, 0, 0, 1, 1, 0);

    logsoftmax_kernel<<<M_, 256, V_ * 4>>>(out);
}